// round 13
// baseline (speedup 1.0000x reference)
#include <cuda_runtime.h>
#include <cstdint>
#include <math.h>

#define N_NODES 10000
#define E_EDGES 640000
#define DIM     128
#define HEADS   4

// device globals zero-init at load; consumers re-zero what they read.
__device__ float g_M[128 * 512];         // M[c][h*128+k], scale folded
__device__ float g_B[512];               // B[h*128+k], scale folded
__device__ float g_Mb[128 * 4];          // Mb[c][h], scale folded
__device__ float g_cb[4];                // scale folded
__device__ float g_wt[N_NODES * 512];    // w-tilde [n][h*128+k]
__device__ float g_c[N_NODES * HEADS];
__device__ float g_S[N_NODES * 512];     // self-cleaned by k_vproj
__device__ float g_agg[N_NODES * DIM];
__device__ float g_den[N_NODES * HEADS]; // self-cleaned by k_vproj
__device__ int   g_cnt[N_NODES];         // self-cleaned by k_scan
__device__ int   g_cur[N_NODES];         // fully rewritten by k_scan
__device__ int   g_perm[E_EDGES];        // fully rewritten by scatter

__device__ __forceinline__ int detect32(const void* ei) {
    const long long* p = (const long long*)ei;
    long long x = 0;
    #pragma unroll
    for (int i = 0; i < 8; i++) x |= p[i];
    return (((unsigned long long)x) >> 32) != 0ull;
}
__device__ __forceinline__ int dst_at(const void* ei, int e, int is32) {
    return is32 ? ((const int*)ei)[e] : (int)((const long long*)ei)[e];
}

// ---------------- launch 0: prep (blocks [0,32)) + hist (rest); NO smem ----------------
__global__ __launch_bounds__(256) void k_hist_prep(const float* __restrict__ Wq,
                                                   const float* __restrict__ bq,
                                                   const float* __restrict__ Wk,
                                                   const float* __restrict__ bk,
                                                   const void* __restrict__ ei, int E) {
    const float scale = 0.17677669529663689f;  // 1/sqrt(32)
    int tid = threadIdx.x;
    if ((int)blockIdx.x >= 32) {
        __shared__ int s32;
        if (tid == 0) s32 = detect32(ei);
        __syncthreads();
        int e = (blockIdx.x - 32) * blockDim.x + tid;
        if (e < E) atomicAdd(&g_cnt[dst_at(ei, e, s32)], 1);
        return;
    }
    int b = blockIdx.x;
    int c = tid & 127, kp = tid >> 7;
    #pragma unroll
    for (int h = 0; h < 4; h++) {
        float wq[32];
        #pragma unroll
        for (int d4 = 0; d4 < 8; d4++) {
            float4 v = __ldg((const float4*)&Wq[c * 128 + h * 32 + d4 * 4]);
            wq[d4 * 4 + 0] = v.x; wq[d4 * 4 + 1] = v.y;
            wq[d4 * 4 + 2] = v.z; wq[d4 * 4 + 3] = v.w;
        }
        #pragma unroll
        for (int j = 0; j < 2; j++) {
            int kl = 2 * kp + j;
            float s = 0.f;
            #pragma unroll
            for (int d = 0; d < 32; d++)
                s += wq[d] * __ldg(&Wk[(b * 4 + kl) * 128 + h * 32 + d]);
            g_M[c * 512 + h * 128 + b * 4 + kl] = s * scale;
        }
    }
    if (tid < 16) {
        int kl = tid >> 2, h = tid & 3;
        float s = 0.f;
        #pragma unroll
        for (int d = 0; d < 32; d++)
            s += __ldg(&bq[h * 32 + d]) * __ldg(&Wk[(b * 4 + kl) * 128 + h * 32 + d]);
        g_B[h * 128 + b * 4 + kl] = s * scale;
    }
    if (b == 0) {
        int hp = tid >> 7;
        #pragma unroll
        for (int j = 0; j < 2; j++) {
            int h = 2 * hp + j;
            float s = 0.f;
            #pragma unroll
            for (int d = 0; d < 32; d++)
                s += __ldg(&Wq[c * 128 + h * 32 + d]) * __ldg(&bk[h * 32 + d]);
            g_Mb[c * 4 + h] = s * scale;
        }
        if (tid < 4) {
            float s = 0.f;
            #pragma unroll
            for (int d = 0; d < 32; d++) s += __ldg(&bq[tid * 32 + d]) * __ldg(&bk[tid * 32 + d]);
            g_cb[tid] = s * scale;
        }
    }
}

// ---------------- launch 1: scan (+ self-clean g_cnt) ----------------
__global__ __launch_bounds__(1024) void k_scan(int n) {
    __shared__ int ws[32];
    int t = threadIdx.x, lane = t & 31, wd = t >> 5;
    int per = (n + 1023) / 1024;
    int base = t * per;
    int s = 0;
    for (int i = 0; i < per; i++) {
        int idx = base + i;
        if (idx < n) s += g_cnt[idx];
    }
    int incl = s;
    #pragma unroll
    for (int off = 1; off < 32; off <<= 1) {
        int y = __shfl_up_sync(0xffffffffu, incl, off);
        if (lane >= off) incl += y;
    }
    if (lane == 31) ws[wd] = incl;
    __syncthreads();
    if (wd == 0) {
        int v = ws[lane];
        int iv = v;
        #pragma unroll
        for (int off = 1; off < 32; off <<= 1) {
            int y = __shfl_up_sync(0xffffffffu, iv, off);
            if (lane >= off) iv += y;
        }
        ws[lane] = iv - v;
    }
    __syncthreads();
    int run = ws[wd] + incl - s;
    for (int i = 0; i < per; i++) {
        int idx = base + i;
        if (idx < n) {
            int v = g_cnt[idx];
            g_cur[idx] = run;
            run += v;
            g_cnt[idx] = 0;
        }
    }
}

// ---------------- launch 2: scatter ----------------
__global__ void k_scatter(const void* __restrict__ ei, int E) {
    __shared__ int s32;
    if (threadIdx.x == 0) s32 = detect32(ei);
    __syncthreads();
    int e = blockIdx.x * blockDim.x + threadIdx.x;
    if (e < E) {
        int pos = atomicAdd(&g_cur[dst_at(ei, e, s32)], 1);
        g_perm[pos] = e;
    }
}

// ---------------- launch 3 (PROFILED): k_wt — wt = X@M + B (64 rows/block, 4 col slices) ----------------
__global__ __launch_bounds__(256) void k_wt(const float* __restrict__ X, int n) {
    extern __shared__ float sv[];
    float* As = sv;               // [64][132]
    int tid = threadIdx.x;
    int b = blockIdx.x;
    int row0 = (b >> 2) * 64;
    int by = b & 3;

    for (int i = tid; i < 64 * DIM; i += 256) {
        int r = i >> 7, c = i & 127;
        int gr = row0 + r;
        As[r * 132 + c] = (gr < n) ? X[gr * DIM + c] : 0.f;
    }
    __syncthreads();

    int cg = (tid & 31) * 4, rg = (tid >> 5) * 8;
    float acc[8][4] = {};
    #pragma unroll 4
    for (int d = 0; d < DIM; d++) {
        float4 w = __ldg((const float4*)&g_M[d * 512 + by * 128 + cg]);
        #pragma unroll
        for (int rr = 0; rr < 8; rr++) {
            float a = As[(rg + rr) * 132 + d];
            acc[rr][0] += a * w.x; acc[rr][1] += a * w.y;
            acc[rr][2] += a * w.z; acc[rr][3] += a * w.w;
        }
    }
    float4 bb = __ldg((const float4*)&g_B[by * 128 + cg]);
    #pragma unroll
    for (int rr = 0; rr < 8; rr++) {
        int gr = row0 + rg + rr;
        if (gr < n) {
            float4 o = make_float4(acc[rr][0] + bb.x, acc[rr][1] + bb.y,
                                   acc[rr][2] + bb.z, acc[rr][3] + bb.w);
            *(float4*)&g_wt[(size_t)gr * 512 + by * 128 + cg] = o;
        }
    }
    if (by == 0) {
        int nl = tid >> 2, h = tid & 3;
        int node = row0 + nl;
        float s = 0.f;
        #pragma unroll 8
        for (int c = 0; c < 128; c++) s += As[nl * 132 + c] * __ldg(&g_Mb[c * 4 + h]);
        if (node < n) g_c[node * 4 + h] = s + g_cb[h];
    }
}

// ---------------- launch 4: k_edge — fused, coalesced, 9-shfl reduce ----------------
// Lane owns bytes [lane*16, lane*16+16) of each 512B row (1 LDG.128 per row).
// Warp handles 64 perm-contiguous edges, depth-2 prefetch.
__global__ __launch_bounds__(256, 3) void k_edge(const float* __restrict__ ke,
                                                 const float* __restrict__ ve,
                                                 const void* __restrict__ ei, int E) {
    __shared__ int s32s;
    if (threadIdx.x == 0) s32s = detect32(ei);
    __syncthreads();
    int is32 = s32s;
    int lane = threadIdx.x & 31;
    int hs = lane & 3;                       // this lane's "score head"
    int gw = (blockIdx.x * blockDim.x + threadIdx.x) >> 5;
    int base = gw * 64;
    if (base >= E) return;
    int cnt = min(64, E - base);

    int pe_l[2], d_l[2];
    #pragma unroll
    for (int j = 0; j < 2; j++) {
        int idx = base + j * 32 + lane;
        if (idx < E) {
            pe_l[j] = g_perm[idx];
            d_l[j] = dst_at(ei, pe_l[j], is32);
        } else { pe_l[j] = 0; d_l[j] = -1; }
    }

    const float4* keL = (const float4*)ke + lane;
    const float4* veL = (const float4*)ve + lane;

    int i1 = (1 < cnt) ? 1 : 0;
    int pa = __shfl_sync(0xffffffffu, pe_l[0], 0);
    int pb = __shfl_sync(0xffffffffu, pe_l[i1 >> 5], i1 & 31);
    float4 k0 = __ldg(keL + (size_t)pa * 32), v0 = __ldg(veL + (size_t)pa * 32);
    float4 k1 = __ldg(keL + (size_t)pb * 32), v1 = __ldg(veL + (size_t)pb * 32);

    float4 wt0, wt1, wt2, wt3;               // wt for heads 0..3 at lane's 4 elems
    wt0 = wt1 = wt2 = wt3 = make_float4(0.f, 0.f, 0.f, 0.f);
    float c_h = 0.f;                         // g_c for head hs of current dst
    float4 a0 = make_float4(0.f, 0.f, 0.f, 0.f), a1 = a0, a2 = a0, a3 = a0;
    float aden = 0.f;                        // per-lane: full segment sum for head hs
    int prevd = -1;

    for (int i = 0; i < cnt; i++) {
        int inx = (i + 2 < cnt) ? i + 2 : i;
        int pn = __shfl_sync(0xffffffffu, pe_l[inx >> 5], inx & 31);
        float4 k2 = __ldg(keL + (size_t)pn * 32);
        float4 v2 = __ldg(veL + (size_t)pn * 32);

        int d = __shfl_sync(0xffffffffu, d_l[i >> 5], i & 31);
        if (d != prevd) {
            if (prevd >= 0) {
                float* S = g_S + (size_t)prevd * 512 + lane * 4;
                atomicAdd(S + 0,   a0.x); atomicAdd(S + 1,   a0.y); atomicAdd(S + 2,   a0.z); atomicAdd(S + 3,   a0.w);
                atomicAdd(S + 128, a1.x); atomicAdd(S + 129, a1.y); atomicAdd(S + 130, a1.z); atomicAdd(S + 131, a1.w);
                atomicAdd(S + 256, a2.x); atomicAdd(S + 257, a2.y); atomicAdd(S + 258, a2.z); atomicAdd(S + 259, a2.w);
                atomicAdd(S + 384, a3.x); atomicAdd(S + 385, a3.y); atomicAdd(S + 386, a3.z); atomicAdd(S + 387, a3.w);
                if (lane < 4) atomicAdd(&g_den[prevd * 4 + lane], aden);
                a0 = a1 = a2 = a3 = make_float4(0.f, 0.f, 0.f, 0.f);
                aden = 0.f;
            }
            const float4* bw = (const float4*)(g_wt + (size_t)d * 512) + lane;
            wt0 = __ldg(bw); wt1 = __ldg(bw + 32); wt2 = __ldg(bw + 64); wt3 = __ldg(bw + 96);
            c_h = __ldg(&g_c[d * 4 + hs]);
            prevd = d;
        }

        // per-lane partial dots for the 4 heads
        float q0 = k0.x * wt0.x + k0.y * wt0.y + k0.z * wt0.z + k0.w * wt0.w;
        float q1 = k0.x * wt1.x + k0.y * wt1.y + k0.z * wt1.z + k0.w * wt1.w;
        float q2 = k0.x * wt2.x + k0.y * wt2.y + k0.z * wt2.z + k0.w * wt2.w;
        float q3 = k0.x * wt3.x + k0.y * wt3.y + k0.z * wt3.z + k0.w * wt3.w;

        // value-folding butterfly: 6 shfl; lane ends with head (lane&3) full sum
        float ta = (lane & 1) ? q0 : q1;
        float ra = __shfl_xor_sync(0xffffffffu, ta, 1);
        float fa = ((lane & 1) ? q1 : q0) + ra;
        float tb = (lane & 1) ? q2 : q3;
        float rb = __shfl_xor_sync(0xffffffffu, tb, 1);
        float fb = ((lane & 1) ? q3 : q2) + rb;
        float tc = (lane & 2) ? fa : fb;
        float rc = __shfl_xor_sync(0xffffffffu, tc, 2);
        float fc = ((lane & 2) ? fb : fa) + rc;
        fc += __shfl_xor_sync(0xffffffffu, fc, 4);
        fc += __shfl_xor_sync(0xffffffffu, fc, 8);
        fc += __shfl_xor_sync(0xffffffffu, fc, 16);

        float e = __expf(fc + c_h);          // e for head hs (warp has all 4 across lanes)

        // re-gather all 4 head e's into every lane: 3 shfl + selects
        float s1 = __shfl_xor_sync(0xffffffffu, e, 1);
        float e_even = (lane & 1) ? s1 : e;
        float e_odd  = (lane & 1) ? e : s1;
        float s2e = __shfl_xor_sync(0xffffffffu, e_even, 2);
        float s2o = __shfl_xor_sync(0xffffffffu, e_odd, 2);
        float e0 = (lane & 2) ? s2e : e_even;
        float e2 = (lane & 2) ? e_even : s2e;
        float e1 = (lane & 2) ? s2o : e_odd;
        float e3 = (lane & 2) ? e_odd : s2o;

        a0.x += e0 * v0.x; a0.y += e0 * v0.y; a0.z += e0 * v0.z; a0.w += e0 * v0.w;
        a1.x += e1 * v0.x; a1.y += e1 * v0.y; a1.z += e1 * v0.z; a1.w += e1 * v0.w;
        a2.x += e2 * v0.x; a2.y += e2 * v0.y; a2.z += e2 * v0.z; a2.w += e2 * v0.w;
        a3.x += e3 * v0.x; a3.y += e3 * v0.y; a3.z += e3 * v0.z; a3.w += e3 * v0.w;
        aden += (hs == 0) ? e0 : (hs == 1) ? e1 : (hs == 2) ? e2 : e3;

        k0 = k1; v0 = v1; k1 = k2; v1 = v2;
    }
    // final flush
    {
        float* S = g_S + (size_t)prevd * 512 + lane * 4;
        atomicAdd(S + 0,   a0.x); atomicAdd(S + 1,   a0.y); atomicAdd(S + 2,   a0.z); atomicAdd(S + 3,   a0.w);
        atomicAdd(S + 128, a1.x); atomicAdd(S + 129, a1.y); atomicAdd(S + 130, a1.z); atomicAdd(S + 131, a1.w);
        atomicAdd(S + 256, a2.x); atomicAdd(S + 257, a2.y); atomicAdd(S + 258, a2.z); atomicAdd(S + 259, a2.w);
        atomicAdd(S + 384, a3.x); atomicAdd(S + 385, a3.y); atomicAdd(S + 386, a3.z); atomicAdd(S + 387, a3.w);
        if (lane < 4) atomicAdd(&g_den[prevd * 4 + lane], aden);
    }
}

// ---------------- launch 5: agg = (S @ Wv)/den + bv (+ self-clean; smem = Ss only) ----------------
__global__ __launch_bounds__(256) void k_vproj(const float* __restrict__ Wv,
                                               const float* __restrict__ bv, int n) {
    extern __shared__ float sq[];
    float* Ss = sq;               // [32][4][136]
    int tid = threadIdx.x;
    int row0 = blockIdx.x * 32;
    for (int i = tid; i < 32 * 512; i += 256) {
        int nl = i >> 9, rest = i & 511;
        int h = rest >> 7, d = rest & 127;
        int gr = row0 + nl;
        float v = 0.f;
        if (gr < n) {
            size_t idx = (size_t)gr * 512 + rest;
            v = g_S[idx];
            g_S[idx] = 0.f;
        }
        Ss[nl * 544 + h * 136 + d] = v;
    }
    __syncthreads();
    int cg = (tid & 31) * 4, rg = (tid >> 5) * 4;
    int h = cg >> 5;
    float acc[4][4] = {};
    #pragma unroll 8
    for (int d = 0; d < DIM; d++) {
        float4 wv = __ldg((const float4*)&Wv[d * DIM + cg]);
        float a0 = Ss[(rg + 0) * 544 + h * 136 + d];
        float a1 = Ss[(rg + 1) * 544 + h * 136 + d];
        float a2 = Ss[(rg + 2) * 544 + h * 136 + d];
        float a3 = Ss[(rg + 3) * 544 + h * 136 + d];
        acc[0][0] += a0 * wv.x; acc[0][1] += a0 * wv.y; acc[0][2] += a0 * wv.z; acc[0][3] += a0 * wv.w;
        acc[1][0] += a1 * wv.x; acc[1][1] += a1 * wv.y; acc[1][2] += a1 * wv.z; acc[1][3] += a1 * wv.w;
        acc[2][0] += a2 * wv.x; acc[2][1] += a2 * wv.y; acc[2][2] += a2 * wv.z; acc[2][3] += a2 * wv.w;
        acc[3][0] += a3 * wv.x; acc[3][1] += a3 * wv.y; acc[3][2] += a3 * wv.z; acc[3][3] += a3 * wv.w;
    }
    float4 bb = __ldg((const float4*)&bv[cg]);
    #pragma unroll
    for (int rr = 0; rr < 4; rr++) {
        int gr = row0 + rg + rr;
        if (gr < n) {
            float den = g_den[gr * HEADS + h];
            float4 o;
            if (den > 0.f) {
                float inv = 1.f / den;
                o = make_float4(acc[rr][0] * inv + bb.x, acc[rr][1] * inv + bb.y,
                                acc[rr][2] * inv + bb.z, acc[rr][3] * inv + bb.w);
            } else {
                o = make_float4(0.f, 0.f, 0.f, 0.f);
            }
            *(float4*)&g_agg[gr * DIM + cg] = o;
        }
    }
    __syncthreads();
    for (int i = tid; i < 32 * HEADS; i += 256) {
        int gr = row0 + (i >> 2);
        if (gr < n) g_den[gr * HEADS + (i & 3)] = 0.f;
    }
}

// ---------------- launch 6: out = agg @ Wo + bo (smem = As only) ----------------
__global__ __launch_bounds__(256) void k_out(const float* __restrict__ W,
                                             const float* __restrict__ b,
                                             float* __restrict__ Y, int n) {
    extern __shared__ float so[];
    float* As = so;               // [32][132]
    int tid = threadIdx.x;
    int row0 = blockIdx.x * 32;
    for (int i = tid; i < 32 * DIM; i += 256) {
        int r = i >> 7, c = i & 127;
        int gr = row0 + r;
        As[r * 132 + c] = (gr < n) ? g_agg[gr * DIM + c] : 0.f;
    }
    __syncthreads();
    int cg = (tid & 31) * 4, rg = (tid >> 5) * 4;
    float acc[4][4] = {};
    #pragma unroll 8
    for (int d = 0; d < DIM; d++) {
        float4 w = __ldg((const float4*)&W[d * DIM + cg]);
        float a0 = As[(rg + 0) * 132 + d];
        float a1 = As[(rg + 1) * 132 + d];
        float a2 = As[(rg + 2) * 132 + d];
        float a3 = As[(rg + 3) * 132 + d];
        acc[0][0] += a0 * w.x; acc[0][1] += a0 * w.y; acc[0][2] += a0 * w.z; acc[0][3] += a0 * w.w;
        acc[1][0] += a1 * w.x; acc[1][1] += a1 * w.y; acc[1][2] += a1 * w.z; acc[1][3] += a1 * w.w;
        acc[2][0] += a2 * w.x; acc[2][1] += a2 * w.y; acc[2][2] += a2 * w.z; acc[2][3] += a2 * w.w;
        acc[3][0] += a3 * w.x; acc[3][1] += a3 * w.y; acc[3][2] += a3 * w.z; acc[3][3] += a3 * w.w;
    }
    float4 bb = __ldg((const float4*)&b[cg]);
    #pragma unroll
    for (int rr = 0; rr < 4; rr++) {
        int gr = row0 + rg + rr;
        if (gr < n) {
            float4 o = make_float4(acc[rr][0] + bb.x, acc[rr][1] + bb.y,
                                   acc[rr][2] + bb.z, acc[rr][3] + bb.w);
            *(float4*)&Y[gr * DIM + cg] = o;
        }
    }
}

extern "C" void kernel_launch(void* const* d_in, const int* in_sizes, int n_in,
                              void* d_out, int out_size) {
    const float* q_nodes = (const float*)d_in[0];
    const float* k_edges = (const float*)d_in[1];
    const float* v_edges = (const float*)d_in[2];
    const float* Wq = (const float*)d_in[3];
    const float* bq = (const float*)d_in[4];
    const float* Wk = (const float*)d_in[5];
    const float* bk = (const float*)d_in[6];
    const float* Wv = (const float*)d_in[7];
    const float* bv = (const float*)d_in[8];
    const float* Wo = (const float*)d_in[9];
    const float* bo = (const float*)d_in[10];
    const void*  ei = (const void*)d_in[11];

    int N = in_sizes[0] / DIM;
    int E = in_sizes[1] / DIM;

    const int smem_ws  = 64 * 132 * (int)sizeof(float);   // 33792
    const int smem_vp  = 32 * 544 * (int)sizeof(float);   // 69632
    const int smem_out = 32 * 132 * (int)sizeof(float);   // 16896
    cudaFuncSetAttribute(k_wt, cudaFuncAttributeMaxDynamicSharedMemorySize, smem_ws);
    cudaFuncSetAttribute(k_vproj, cudaFuncAttributeMaxDynamicSharedMemorySize, smem_vp);
    cudaFuncSetAttribute(k_out, cudaFuncAttributeMaxDynamicSharedMemorySize, smem_out);

    int nblk = (N + 31) / 32;
    int histBlocks = (E + 255) / 256;
    int wtBlocks = ((N + 63) / 64) * 4;
    int ewarps = (E + 63) / 64;
    int eblocks = (ewarps + 7) / 8;

    k_hist_prep<<<32 + histBlocks, 256>>>(Wq, bq, Wk, bk, ei, E);      // 0
    k_scan<<<1, 1024>>>(N);                                            // 1
    k_scatter<<<histBlocks, 256>>>(ei, E);                             // 2
    k_wt<<<wtBlocks, 256, smem_ws>>>(q_nodes, N);                      // 3 (profiled)
    k_edge<<<eblocks, 256>>>(k_edges, v_edges, ei, E);                 // 4
    k_vproj<<<nblk, 256, smem_vp>>>(Wv, bv, N);                        // 5
    k_out<<<nblk, 256, smem_out>>>(Wo, bo, (float*)d_out, N);          // 6
}

// round 14
// speedup vs baseline: 1.1507x; 1.1507x over previous
#include <cuda_runtime.h>
#include <cstdint>
#include <math.h>

#define N_NODES 10000
#define E_EDGES 640000
#define DIM     128
#define HEADS   4

// device globals zero-init at load; consumers re-zero what they read.
__device__ float g_M[128 * 512];         // M[c][h*128+k], scale folded
__device__ float g_B[512];               // B[h*128+k], scale folded
__device__ float g_Mb[128 * 4];          // Mb[c][h], scale folded
__device__ float g_cb[4];                // scale folded
__device__ float g_wt[N_NODES * 512];    // w-tilde [n][h*128+k]
__device__ float g_c[N_NODES * HEADS];
__device__ float g_S[N_NODES * 512];     // self-cleaned by k_post
__device__ float g_den[N_NODES * HEADS]; // self-cleaned by k_post
__device__ int   g_cnt[N_NODES];         // self-cleaned by k_scan
__device__ int   g_cur[N_NODES];         // fully rewritten by k_scan
__device__ int   g_perm[E_EDGES];        // fully rewritten by scatter

__device__ __forceinline__ int detect32(const void* ei) {
    const long long* p = (const long long*)ei;
    long long x = 0;
    #pragma unroll
    for (int i = 0; i < 8; i++) x |= p[i];
    return (((unsigned long long)x) >> 32) != 0ull;
}
__device__ __forceinline__ int dst_at(const void* ei, int e, int is32) {
    return is32 ? ((const int*)ei)[e] : (int)((const long long*)ei)[e];
}

// ---------------- launch 0: prep (blocks [0,32)) + hist (rest); NO smem ----------------
__global__ __launch_bounds__(256) void k_hist_prep(const float* __restrict__ Wq,
                                                   const float* __restrict__ bq,
                                                   const float* __restrict__ Wk,
                                                   const float* __restrict__ bk,
                                                   const void* __restrict__ ei, int E) {
    const float scale = 0.17677669529663689f;  // 1/sqrt(32)
    int tid = threadIdx.x;
    if ((int)blockIdx.x >= 32) {
        __shared__ int s32;
        if (tid == 0) s32 = detect32(ei);
        __syncthreads();
        int e = (blockIdx.x - 32) * blockDim.x + tid;
        if (e < E) atomicAdd(&g_cnt[dst_at(ei, e, s32)], 1);
        return;
    }
    int b = blockIdx.x;
    int c = tid & 127, kp = tid >> 7;
    #pragma unroll
    for (int h = 0; h < 4; h++) {
        float wq[32];
        #pragma unroll
        for (int d4 = 0; d4 < 8; d4++) {
            float4 v = __ldg((const float4*)&Wq[c * 128 + h * 32 + d4 * 4]);
            wq[d4 * 4 + 0] = v.x; wq[d4 * 4 + 1] = v.y;
            wq[d4 * 4 + 2] = v.z; wq[d4 * 4 + 3] = v.w;
        }
        #pragma unroll
        for (int j = 0; j < 2; j++) {
            int kl = 2 * kp + j;
            float s = 0.f;
            #pragma unroll
            for (int d = 0; d < 32; d++)
                s += wq[d] * __ldg(&Wk[(b * 4 + kl) * 128 + h * 32 + d]);
            g_M[c * 512 + h * 128 + b * 4 + kl] = s * scale;
        }
    }
    if (tid < 16) {
        int kl = tid >> 2, h = tid & 3;
        float s = 0.f;
        #pragma unroll
        for (int d = 0; d < 32; d++)
            s += __ldg(&bq[h * 32 + d]) * __ldg(&Wk[(b * 4 + kl) * 128 + h * 32 + d]);
        g_B[h * 128 + b * 4 + kl] = s * scale;
    }
    if (b == 0) {
        int hp = tid >> 7;
        #pragma unroll
        for (int j = 0; j < 2; j++) {
            int h = 2 * hp + j;
            float s = 0.f;
            #pragma unroll
            for (int d = 0; d < 32; d++)
                s += __ldg(&Wq[c * 128 + h * 32 + d]) * __ldg(&bk[h * 32 + d]);
            g_Mb[c * 4 + h] = s * scale;
        }
        if (tid < 4) {
            float s = 0.f;
            #pragma unroll
            for (int d = 0; d < 32; d++) s += __ldg(&bq[tid * 32 + d]) * __ldg(&bk[tid * 32 + d]);
            g_cb[tid] = s * scale;
        }
    }
}

// ---------------- launch 1: scan (+ self-clean g_cnt) ----------------
__global__ __launch_bounds__(1024) void k_scan(int n) {
    __shared__ int ws[32];
    int t = threadIdx.x, lane = t & 31, wd = t >> 5;
    int per = (n + 1023) / 1024;
    int base = t * per;
    int s = 0;
    for (int i = 0; i < per; i++) {
        int idx = base + i;
        if (idx < n) s += g_cnt[idx];
    }
    int incl = s;
    #pragma unroll
    for (int off = 1; off < 32; off <<= 1) {
        int y = __shfl_up_sync(0xffffffffu, incl, off);
        if (lane >= off) incl += y;
    }
    if (lane == 31) ws[wd] = incl;
    __syncthreads();
    if (wd == 0) {
        int v = ws[lane];
        int iv = v;
        #pragma unroll
        for (int off = 1; off < 32; off <<= 1) {
            int y = __shfl_up_sync(0xffffffffu, iv, off);
            if (lane >= off) iv += y;
        }
        ws[lane] = iv - v;
    }
    __syncthreads();
    int run = ws[wd] + incl - s;
    for (int i = 0; i < per; i++) {
        int idx = base + i;
        if (idx < n) {
            int v = g_cnt[idx];
            g_cur[idx] = run;
            run += v;
            g_cnt[idx] = 0;
        }
    }
}

// ---------------- launch 2: k_wt (smem = As only) + scatter ----------------
__global__ __launch_bounds__(256) void k_wt_scatter(const float* __restrict__ X,
                                                    const void* __restrict__ ei,
                                                    int n, int E, int wtBlocks) {
    if ((int)blockIdx.x >= wtBlocks) {
        __shared__ int s32;
        if (threadIdx.x == 0) s32 = detect32(ei);
        __syncthreads();
        int e = (blockIdx.x - wtBlocks) * blockDim.x + threadIdx.x;
        if (e < E) {
            int pos = atomicAdd(&g_cur[dst_at(ei, e, s32)], 1);
            g_perm[pos] = e;
        }
        return;
    }
    extern __shared__ float sv[];
    float* As = sv;               // [64][132]
    int tid = threadIdx.x;
    int b = blockIdx.x;
    int row0 = (b >> 2) * 64;
    int by = b & 3;

    for (int i = tid; i < 64 * DIM; i += 256) {
        int r = i >> 7, c = i & 127;
        int gr = row0 + r;
        As[r * 132 + c] = (gr < n) ? X[gr * DIM + c] : 0.f;
    }
    __syncthreads();

    int cg = (tid & 31) * 4, rg = (tid >> 5) * 8;
    float acc[8][4] = {};
    #pragma unroll 4
    for (int d = 0; d < DIM; d++) {
        float4 w = __ldg((const float4*)&g_M[d * 512 + by * 128 + cg]);
        #pragma unroll
        for (int rr = 0; rr < 8; rr++) {
            float a = As[(rg + rr) * 132 + d];
            acc[rr][0] += a * w.x; acc[rr][1] += a * w.y;
            acc[rr][2] += a * w.z; acc[rr][3] += a * w.w;
        }
    }
    float4 bb = __ldg((const float4*)&g_B[by * 128 + cg]);
    #pragma unroll
    for (int rr = 0; rr < 8; rr++) {
        int gr = row0 + rg + rr;
        if (gr < n) {
            float4 o = make_float4(acc[rr][0] + bb.x, acc[rr][1] + bb.y,
                                   acc[rr][2] + bb.z, acc[rr][3] + bb.w);
            *(float4*)&g_wt[(size_t)gr * 512 + by * 128 + cg] = o;
        }
    }
    if (by == 0) {
        int nl = tid >> 2, h = tid & 3;
        int node = row0 + nl;
        float s = 0.f;
        #pragma unroll 8
        for (int c = 0; c < 128; c++) s += As[nl * 132 + c] * __ldg(&g_Mb[c * 4 + h]);
        if (node < n) g_c[node * 4 + h] = s + g_cb[h];
    }
}

// ---------------- k_edge helpers ----------------
// full score pipeline for one edge: 4 partial dots -> all-4-head e's in every lane
__device__ __forceinline__ float4 score4(float q0, float q1, float q2, float q3,
                                         int lane, float c_h) {
    float ta = (lane & 1) ? q0 : q1;
    float ra = __shfl_xor_sync(0xffffffffu, ta, 1);
    float fa = ((lane & 1) ? q1 : q0) + ra;
    float tb = (lane & 1) ? q2 : q3;
    float rb = __shfl_xor_sync(0xffffffffu, tb, 1);
    float fb = ((lane & 1) ? q3 : q2) + rb;
    float tc = (lane & 2) ? fa : fb;
    float rc = __shfl_xor_sync(0xffffffffu, tc, 2);
    float fc = ((lane & 2) ? fb : fa) + rc;
    fc += __shfl_xor_sync(0xffffffffu, fc, 4);
    fc += __shfl_xor_sync(0xffffffffu, fc, 8);
    fc += __shfl_xor_sync(0xffffffffu, fc, 16);
    float e = __expf(fc + c_h);
    float s1 = __shfl_xor_sync(0xffffffffu, e, 1);
    float e_even = (lane & 1) ? s1 : e;
    float e_odd  = (lane & 1) ? e : s1;
    float s2e = __shfl_xor_sync(0xffffffffu, e_even, 2);
    float s2o = __shfl_xor_sync(0xffffffffu, e_odd, 2);
    float4 r;
    r.x = (lane & 2) ? s2e : e_even;
    r.z = (lane & 2) ? e_even : s2e;
    r.y = (lane & 2) ? s2o : e_odd;
    r.w = (lane & 2) ? e_odd : s2o;
    return r;
}

// ---------------- launch 3 (PROFILED): k_edge — pairwise-interleaved score chains ----------------
__global__ __launch_bounds__(256, 3) void k_edge(const float* __restrict__ ke,
                                                 const float* __restrict__ ve,
                                                 const void* __restrict__ ei, int E) {
    __shared__ int s32s;
    if (threadIdx.x == 0) s32s = detect32(ei);
    __syncthreads();
    int is32 = s32s;
    int lane = threadIdx.x & 31;
    int hs = lane & 3;
    int gw = (blockIdx.x * blockDim.x + threadIdx.x) >> 5;
    int base = gw * 64;
    if (base >= E) return;
    int cnt = min(64, E - base);

    int pe_l[2], d_l[2];
    #pragma unroll
    for (int j = 0; j < 2; j++) {
        int idx = base + j * 32 + lane;
        if (idx < E) {
            pe_l[j] = g_perm[idx];
            d_l[j] = dst_at(ei, pe_l[j], is32);
        } else { pe_l[j] = 0; d_l[j] = -1; }
    }

    const float4* keL = (const float4*)ke + lane;
    const float4* veL = (const float4*)ve + lane;

    // load first pair
    int i1 = (1 < cnt) ? 1 : 0;
    int pa = __shfl_sync(0xffffffffu, pe_l[0], 0);
    int pb = __shfl_sync(0xffffffffu, pe_l[i1 >> 5], i1 & 31);
    float4 k0 = __ldg(keL + (size_t)pa * 32), v0 = __ldg(veL + (size_t)pa * 32);
    float4 k1 = __ldg(keL + (size_t)pb * 32), v1 = __ldg(veL + (size_t)pb * 32);

    float4 wt0, wt1, wt2, wt3;
    wt0 = wt1 = wt2 = wt3 = make_float4(0.f, 0.f, 0.f, 0.f);
    float c_h = 0.f;
    float4 a0 = make_float4(0.f, 0.f, 0.f, 0.f), a1 = a0, a2 = a0, a3 = a0;
    float aden = 0.f;
    int prevd = -1;

    #define LOADWT(dd) do { \
        const float4* bw = (const float4*)(g_wt + (size_t)(dd) * 512) + lane; \
        wt0 = __ldg(bw); wt1 = __ldg(bw + 32); wt2 = __ldg(bw + 64); wt3 = __ldg(bw + 96); \
        c_h = __ldg(&g_c[(dd) * 4 + hs]); \
    } while (0)

    #define FLUSHSEG(dd) do { \
        float* S = g_S + (size_t)(dd) * 512 + lane * 4; \
        atomicAdd(S + 0,   a0.x); atomicAdd(S + 1,   a0.y); atomicAdd(S + 2,   a0.z); atomicAdd(S + 3,   a0.w); \
        atomicAdd(S + 128, a1.x); atomicAdd(S + 129, a1.y); atomicAdd(S + 130, a1.z); atomicAdd(S + 131, a1.w); \
        atomicAdd(S + 256, a2.x); atomicAdd(S + 257, a2.y); atomicAdd(S + 258, a2.z); atomicAdd(S + 259, a2.w); \
        atomicAdd(S + 384, a3.x); atomicAdd(S + 385, a3.y); atomicAdd(S + 386, a3.z); atomicAdd(S + 387, a3.w); \
        if (lane < 4) atomicAdd(&g_den[(dd) * 4 + lane], aden); \
        a0 = a1 = a2 = a3 = make_float4(0.f, 0.f, 0.f, 0.f); \
        aden = 0.f; \
    } while (0)

    #define DOTS(K, r0, r1, r2, r3) do { \
        r0 = K.x * wt0.x + K.y * wt0.y + K.z * wt0.z + K.w * wt0.w; \
        r1 = K.x * wt1.x + K.y * wt1.y + K.z * wt1.z + K.w * wt1.w; \
        r2 = K.x * wt2.x + K.y * wt2.y + K.z * wt2.z + K.w * wt2.w; \
        r3 = K.x * wt3.x + K.y * wt3.y + K.z * wt3.z + K.w * wt3.w; \
    } while (0)

    #define ACCUM(EV, V) do { \
        a0.x += EV.x * V.x; a0.y += EV.x * V.y; a0.z += EV.x * V.z; a0.w += EV.x * V.w; \
        a1.x += EV.y * V.x; a1.y += EV.y * V.y; a1.z += EV.y * V.z; a1.w += EV.y * V.w; \
        a2.x += EV.z * V.x; a2.y += EV.z * V.y; a2.z += EV.z * V.z; a2.w += EV.z * V.w; \
        a3.x += EV.w * V.x; a3.y += EV.w * V.y; a3.z += EV.w * V.z; a3.w += EV.w * V.w; \
        aden += (hs == 0) ? EV.x : (hs == 1) ? EV.y : (hs == 2) ? EV.z : EV.w; \
    } while (0)

    int i = 0;
    for (; i + 1 < cnt; i += 2) {
        // prefetch next pair
        int inx2 = (i + 2 < cnt) ? i + 2 : i;
        int inx3 = (i + 3 < cnt) ? i + 3 : inx2;
        int pn2 = __shfl_sync(0xffffffffu, pe_l[inx2 >> 5], inx2 & 31);
        int pn3 = __shfl_sync(0xffffffffu, pe_l[inx3 >> 5], inx3 & 31);
        float4 k2 = __ldg(keL + (size_t)pn2 * 32);
        float4 v2 = __ldg(veL + (size_t)pn2 * 32);
        float4 k3 = __ldg(keL + (size_t)pn3 * 32);
        float4 v3 = __ldg(veL + (size_t)pn3 * 32);

        int d0 = __shfl_sync(0xffffffffu, d_l[i >> 5], i & 31);
        int d1 = __shfl_sync(0xffffffffu, d_l[(i + 1) >> 5], (i + 1) & 31);

        if (d0 != prevd) {
            if (prevd >= 0) FLUSHSEG(prevd);
            LOADWT(d0);
            prevd = d0;
        }
        float q0, q1, q2, q3;
        DOTS(k0, q0, q1, q2, q3);
        if (d1 == d0) {
            // fast path: two independent score chains, ptxas interleaves
            float p0, p1, p2, p3;
            DOTS(k1, p0, p1, p2, p3);
            float4 eA = score4(q0, q1, q2, q3, lane, c_h);
            float4 eB = score4(p0, p1, p2, p3, lane, c_h);
            ACCUM(eA, v0);
            ACCUM(eB, v1);
        } else {
            float4 eA = score4(q0, q1, q2, q3, lane, c_h);
            ACCUM(eA, v0);
            FLUSHSEG(prevd);
            LOADWT(d1);
            prevd = d1;
            float p0, p1, p2, p3;
            DOTS(k1, p0, p1, p2, p3);
            float4 eB = score4(p0, p1, p2, p3, lane, c_h);
            ACCUM(eB, v1);
        }
        k0 = k2; v0 = v2; k1 = k3; v1 = v3;
    }
    if (i < cnt) {  // odd tail: edge i in k0/v0
        int d0 = __shfl_sync(0xffffffffu, d_l[i >> 5], i & 31);
        if (d0 != prevd) {
            if (prevd >= 0) FLUSHSEG(prevd);
            LOADWT(d0);
            prevd = d0;
        }
        float q0, q1, q2, q3;
        DOTS(k0, q0, q1, q2, q3);
        float4 eA = score4(q0, q1, q2, q3, lane, c_h);
        ACCUM(eA, v0);
    }
    FLUSHSEG(prevd);
    #undef LOADWT
    #undef FLUSHSEG
    #undef DOTS
    #undef ACCUM
}

// ---------------- launch 4: k_post — agg = (S@Wv)/den + bv; out = agg@Wo + bo ----------------
__global__ __launch_bounds__(256) void k_post(const float* __restrict__ Wv,
                                              const float* __restrict__ bv,
                                              const float* __restrict__ Wo,
                                              const float* __restrict__ bo,
                                              float* __restrict__ Y, int n) {
    extern __shared__ float sq[];
    float* Ss = sq;               // [32][4][136]
    float* As = sq + 32 * 544;    // [32][132]
    int tid = threadIdx.x;
    int row0 = blockIdx.x * 32;

    // phase A load: S -> Ss (+ self-clean)
    for (int i = tid; i < 32 * 512; i += 256) {
        int nl = i >> 9, rest = i & 511;
        int h = rest >> 7, d = rest & 127;
        int gr = row0 + nl;
        float v = 0.f;
        if (gr < n) {
            size_t idx = (size_t)gr * 512 + rest;
            v = g_S[idx];
            g_S[idx] = 0.f;
        }
        Ss[nl * 544 + h * 136 + d] = v;
    }
    __syncthreads();

    int cg = (tid & 31) * 4, rg = (tid >> 5) * 4;
    int h = cg >> 5;
    {
        float acc[4][4] = {};
        #pragma unroll 8
        for (int d = 0; d < DIM; d++) {
            float4 wv = __ldg((const float4*)&Wv[d * DIM + cg]);
            float a0 = Ss[(rg + 0) * 544 + h * 136 + d];
            float a1 = Ss[(rg + 1) * 544 + h * 136 + d];
            float a2 = Ss[(rg + 2) * 544 + h * 136 + d];
            float a3 = Ss[(rg + 3) * 544 + h * 136 + d];
            acc[0][0] += a0 * wv.x; acc[0][1] += a0 * wv.y; acc[0][2] += a0 * wv.z; acc[0][3] += a0 * wv.w;
            acc[1][0] += a1 * wv.x; acc[1][1] += a1 * wv.y; acc[1][2] += a1 * wv.z; acc[1][3] += a1 * wv.w;
            acc[2][0] += a2 * wv.x; acc[2][1] += a2 * wv.y; acc[2][2] += a2 * wv.z; acc[2][3] += a2 * wv.w;
            acc[3][0] += a3 * wv.x; acc[3][1] += a3 * wv.y; acc[3][2] += a3 * wv.z; acc[3][3] += a3 * wv.w;
        }
        float4 bb = __ldg((const float4*)&bv[cg]);
        #pragma unroll
        for (int rr = 0; rr < 4; rr++) {
            int gr = row0 + rg + rr;
            float4 o = make_float4(0.f, 0.f, 0.f, 0.f);
            if (gr < n) {
                float den = g_den[gr * HEADS + h];
                if (den > 0.f) {
                    float inv = 1.f / den;
                    o = make_float4(acc[rr][0] * inv + bb.x, acc[rr][1] * inv + bb.y,
                                    acc[rr][2] * inv + bb.z, acc[rr][3] * inv + bb.w);
                }
            }
            As[(rg + rr) * 132 + cg + 0] = o.x;
            As[(rg + rr) * 132 + cg + 1] = o.y;
            As[(rg + rr) * 132 + cg + 2] = o.z;
            As[(rg + rr) * 132 + cg + 3] = o.w;
        }
    }
    __syncthreads();

    // self-clean den (den reads done above)
    for (int i = tid; i < 32 * HEADS; i += 256) {
        int gr = row0 + (i >> 2);
        if (gr < n) g_den[gr * HEADS + (i & 3)] = 0.f;
    }

    // phase B: out = As @ Wo + bo
    {
        float acc[4][4] = {};
        #pragma unroll 8
        for (int d = 0; d < DIM; d++) {
            float4 w = __ldg((const float4*)&Wo[d * DIM + cg]);
            float a0 = As[(rg + 0) * 132 + d];
            float a1 = As[(rg + 1) * 132 + d];
            float a2 = As[(rg + 2) * 132 + d];
            float a3 = As[(rg + 3) * 132 + d];
            acc[0][0] += a0 * w.x; acc[0][1] += a0 * w.y; acc[0][2] += a0 * w.z; acc[0][3] += a0 * w.w;
            acc[1][0] += a1 * w.x; acc[1][1] += a1 * w.y; acc[1][2] += a1 * w.z; acc[1][3] += a1 * w.w;
            acc[2][0] += a2 * w.x; acc[2][1] += a2 * w.y; acc[2][2] += a2 * w.z; acc[2][3] += a2 * w.w;
            acc[3][0] += a3 * w.x; acc[3][1] += a3 * w.y; acc[3][2] += a3 * w.z; acc[3][3] += a3 * w.w;
        }
        float4 bb = __ldg((const float4*)&bo[cg]);
        #pragma unroll
        for (int rr = 0; rr < 4; rr++) {
            int gr = row0 + rg + rr;
            if (gr < n) {
                float4 o = make_float4(acc[rr][0] + bb.x, acc[rr][1] + bb.y,
                                       acc[rr][2] + bb.z, acc[rr][3] + bb.w);
                *(float4*)&Y[gr * DIM + cg] = o;
            }
        }
    }
}

extern "C" void kernel_launch(void* const* d_in, const int* in_sizes, int n_in,
                              void* d_out, int out_size) {
    const float* q_nodes = (const float*)d_in[0];
    const float* k_edges = (const float*)d_in[1];
    const float* v_edges = (const float*)d_in[2];
    const float* Wq = (const float*)d_in[3];
    const float* bq = (const float*)d_in[4];
    const float* Wk = (const float*)d_in[5];
    const float* bk = (const float*)d_in[6];
    const float* Wv = (const float*)d_in[7];
    const float* bv = (const float*)d_in[8];
    const float* Wo = (const float*)d_in[9];
    const float* bo = (const float*)d_in[10];
    const void*  ei = (const void*)d_in[11];

    int N = in_sizes[0] / DIM;
    int E = in_sizes[1] / DIM;

    const int smem_ws   = 64 * 132 * (int)sizeof(float);              // 33792
    const int smem_post = (32 * 544 + 32 * 132) * (int)sizeof(float); // 86528
    cudaFuncSetAttribute(k_wt_scatter, cudaFuncAttributeMaxDynamicSharedMemorySize, smem_ws);
    cudaFuncSetAttribute(k_post, cudaFuncAttributeMaxDynamicSharedMemorySize, smem_post);

    int nblk = (N + 31) / 32;
    int histBlocks = (E + 255) / 256;
    int wtBlocks = ((N + 63) / 64) * 4;
    int ewarps = (E + 63) / 64;
    int eblocks = (ewarps + 7) / 8;

    k_hist_prep<<<32 + histBlocks, 256>>>(Wq, bq, Wk, bk, ei, E);                        // 0
    k_scan<<<1, 1024>>>(N);                                                              // 1
    k_wt_scatter<<<wtBlocks + histBlocks, 256, smem_ws>>>(q_nodes, ei, N, E, wtBlocks);  // 2
    k_edge<<<eblocks, 256>>>(k_edges, v_edges, ei, E);                                   // 3 (profiled)
    k_post<<<nblk, 256, smem_post>>>(Wv, bv, Wo, bo, (float*)d_out, N);                  // 4
}

// round 15
// speedup vs baseline: 1.2226x; 1.0626x over previous
#include <cuda_runtime.h>
#include <cstdint>
#include <math.h>

#define N_NODES 10000
#define E_EDGES 640000
#define DIM     128
#define HEADS   4

// device globals zero-init at load; consumers re-zero what they read.
__device__ float g_M[128 * 512];         // M[c][h*128+k], scale folded
__device__ float g_B[512];               // B[h*128+k], scale folded
__device__ float g_Mb[128 * 4];          // Mb[c][h], scale folded
__device__ float g_cb[4];                // scale folded
__device__ float g_wt[N_NODES * 512];    // w-tilde [n][h*128+k]
__device__ float g_c[N_NODES * HEADS];
__device__ float g_S[N_NODES * 512];     // self-cleaned by k_post
__device__ float g_den[N_NODES * HEADS]; // self-cleaned by k_post
__device__ int   g_cnt[N_NODES];         // self-cleaned by k_scan
__device__ int   g_cur[N_NODES];         // fully rewritten by k_scan
__device__ int   g_perm[E_EDGES];        // fully rewritten by scatter

__device__ __forceinline__ int detect32(const void* ei) {
    const long long* p = (const long long*)ei;
    long long x = 0;
    #pragma unroll
    for (int i = 0; i < 8; i++) x |= p[i];
    return (((unsigned long long)x) >> 32) != 0ull;
}
__device__ __forceinline__ int dst_at(const void* ei, int e, int is32) {
    return is32 ? ((const int*)ei)[e] : (int)((const long long*)ei)[e];
}

// ---------------- launch 0: prep (blocks [0,32)) + hist (rest); NO smem ----------------
__global__ __launch_bounds__(256) void k_hist_prep(const float* __restrict__ Wq,
                                                   const float* __restrict__ bq,
                                                   const float* __restrict__ Wk,
                                                   const float* __restrict__ bk,
                                                   const void* __restrict__ ei, int E) {
    const float scale = 0.17677669529663689f;  // 1/sqrt(32)
    int tid = threadIdx.x;
    if ((int)blockIdx.x >= 32) {
        __shared__ int s32;
        if (tid == 0) s32 = detect32(ei);
        __syncthreads();
        int e = (blockIdx.x - 32) * blockDim.x + tid;
        if (e < E) atomicAdd(&g_cnt[dst_at(ei, e, s32)], 1);
        return;
    }
    int b = blockIdx.x;
    int c = tid & 127, kp = tid >> 7;
    #pragma unroll
    for (int h = 0; h < 4; h++) {
        float wq[32];
        #pragma unroll
        for (int d4 = 0; d4 < 8; d4++) {
            float4 v = __ldg((const float4*)&Wq[c * 128 + h * 32 + d4 * 4]);
            wq[d4 * 4 + 0] = v.x; wq[d4 * 4 + 1] = v.y;
            wq[d4 * 4 + 2] = v.z; wq[d4 * 4 + 3] = v.w;
        }
        #pragma unroll
        for (int j = 0; j < 2; j++) {
            int kl = 2 * kp + j;
            float s = 0.f;
            #pragma unroll
            for (int d = 0; d < 32; d++)
                s += wq[d] * __ldg(&Wk[(b * 4 + kl) * 128 + h * 32 + d]);
            g_M[c * 512 + h * 128 + b * 4 + kl] = s * scale;
        }
    }
    if (tid < 16) {
        int kl = tid >> 2, h = tid & 3;
        float s = 0.f;
        #pragma unroll
        for (int d = 0; d < 32; d++)
            s += __ldg(&bq[h * 32 + d]) * __ldg(&Wk[(b * 4 + kl) * 128 + h * 32 + d]);
        g_B[h * 128 + b * 4 + kl] = s * scale;
    }
    if (b == 0) {
        int hp = tid >> 7;
        #pragma unroll
        for (int j = 0; j < 2; j++) {
            int h = 2 * hp + j;
            float s = 0.f;
            #pragma unroll
            for (int d = 0; d < 32; d++)
                s += __ldg(&Wq[c * 128 + h * 32 + d]) * __ldg(&bk[h * 32 + d]);
            g_Mb[c * 4 + h] = s * scale;
        }
        if (tid < 4) {
            float s = 0.f;
            #pragma unroll
            for (int d = 0; d < 32; d++) s += __ldg(&bq[tid * 32 + d]) * __ldg(&bk[tid * 32 + d]);
            g_cb[tid] = s * scale;
        }
    }
}

// ---------------- launch 1: scan (+ self-clean g_cnt) ----------------
__global__ __launch_bounds__(1024) void k_scan(int n) {
    __shared__ int ws[32];
    int t = threadIdx.x, lane = t & 31, wd = t >> 5;
    int per = (n + 1023) / 1024;
    int base = t * per;
    int s = 0;
    for (int i = 0; i < per; i++) {
        int idx = base + i;
        if (idx < n) s += g_cnt[idx];
    }
    int incl = s;
    #pragma unroll
    for (int off = 1; off < 32; off <<= 1) {
        int y = __shfl_up_sync(0xffffffffu, incl, off);
        if (lane >= off) incl += y;
    }
    if (lane == 31) ws[wd] = incl;
    __syncthreads();
    if (wd == 0) {
        int v = ws[lane];
        int iv = v;
        #pragma unroll
        for (int off = 1; off < 32; off <<= 1) {
            int y = __shfl_up_sync(0xffffffffu, iv, off);
            if (lane >= off) iv += y;
        }
        ws[lane] = iv - v;
    }
    __syncthreads();
    int run = ws[wd] + incl - s;
    for (int i = 0; i < per; i++) {
        int idx = base + i;
        if (idx < n) {
            int v = g_cnt[idx];
            g_cur[idx] = run;
            run += v;
            g_cnt[idx] = 0;
        }
    }
}

// ---------------- launch 2: k_wt (32-row tiles, smem = As only) + scatter ----------------
__global__ __launch_bounds__(256) void k_wt_scatter(const float* __restrict__ X,
                                                    const void* __restrict__ ei,
                                                    int n, int E, int wtBlocks) {
    if ((int)blockIdx.x >= wtBlocks) {
        __shared__ int s32;
        if (threadIdx.x == 0) s32 = detect32(ei);
        __syncthreads();
        int e = (blockIdx.x - wtBlocks) * blockDim.x + threadIdx.x;
        if (e < E) {
            int pos = atomicAdd(&g_cur[dst_at(ei, e, s32)], 1);
            g_perm[pos] = e;
        }
        return;
    }
    extern __shared__ float sv[];
    float* As = sv;               // [32][132]
    int tid = threadIdx.x;
    int b = blockIdx.x;
    int row0 = (b >> 2) * 32;
    int by = b & 3;

    for (int i = tid; i < 32 * DIM; i += 256) {
        int r = i >> 7, c = i & 127;
        int gr = row0 + r;
        As[r * 132 + c] = (gr < n) ? X[gr * DIM + c] : 0.f;
    }
    __syncthreads();

    int cg = (tid & 31) * 4, rg = (tid >> 5) * 4;
    float acc[4][4] = {};
    #pragma unroll 8
    for (int d = 0; d < DIM; d++) {
        float4 w = __ldg((const float4*)&g_M[d * 512 + by * 128 + cg]);
        #pragma unroll
        for (int rr = 0; rr < 4; rr++) {
            float a = As[(rg + rr) * 132 + d];
            acc[rr][0] += a * w.x; acc[rr][1] += a * w.y;
            acc[rr][2] += a * w.z; acc[rr][3] += a * w.w;
        }
    }
    float4 bb = __ldg((const float4*)&g_B[by * 128 + cg]);
    #pragma unroll
    for (int rr = 0; rr < 4; rr++) {
        int gr = row0 + rg + rr;
        if (gr < n) {
            float4 o = make_float4(acc[rr][0] + bb.x, acc[rr][1] + bb.y,
                                   acc[rr][2] + bb.z, acc[rr][3] + bb.w);
            *(float4*)&g_wt[(size_t)gr * 512 + by * 128 + cg] = o;
        }
    }
    if (by == 0 && tid < 128) {
        int nl = tid >> 2, h = tid & 3;
        int node = row0 + nl;
        float s = 0.f;
        #pragma unroll 8
        for (int c = 0; c < 128; c++) s += As[nl * 132 + c] * __ldg(&g_Mb[c * 4 + h]);
        if (node < n) g_c[node * 4 + h] = s + g_cb[h];
    }
}

// ---------------- k_edge helpers ----------------
__device__ __forceinline__ float4 score4(float q0, float q1, float q2, float q3,
                                         int lane, float c_h) {
    float ta = (lane & 1) ? q0 : q1;
    float ra = __shfl_xor_sync(0xffffffffu, ta, 1);
    float fa = ((lane & 1) ? q1 : q0) + ra;
    float tb = (lane & 1) ? q2 : q3;
    float rb = __shfl_xor_sync(0xffffffffu, tb, 1);
    float fb = ((lane & 1) ? q3 : q2) + rb;
    float tc = (lane & 2) ? fa : fb;
    float rc = __shfl_xor_sync(0xffffffffu, tc, 2);
    float fc = ((lane & 2) ? fb : fa) + rc;
    fc += __shfl_xor_sync(0xffffffffu, fc, 4);
    fc += __shfl_xor_sync(0xffffffffu, fc, 8);
    fc += __shfl_xor_sync(0xffffffffu, fc, 16);
    float e = __expf(fc + c_h);
    float s1 = __shfl_xor_sync(0xffffffffu, e, 1);
    float e_even = (lane & 1) ? s1 : e;
    float e_odd  = (lane & 1) ? e : s1;
    float s2e = __shfl_xor_sync(0xffffffffu, e_even, 2);
    float s2o = __shfl_xor_sync(0xffffffffu, e_odd, 2);
    float4 r;
    r.x = (lane & 2) ? s2e : e_even;
    r.z = (lane & 2) ? e_even : s2e;
    r.y = (lane & 2) ? s2o : e_odd;
    r.w = (lane & 2) ? e_odd : s2o;
    return r;
}

// ---------------- launch 3 (PROFILED): k_edge — pairwise-interleaved score chains ----------------
__global__ __launch_bounds__(256, 3) void k_edge(const float* __restrict__ ke,
                                                 const float* __restrict__ ve,
                                                 const void* __restrict__ ei, int E) {
    __shared__ int s32s;
    if (threadIdx.x == 0) s32s = detect32(ei);
    __syncthreads();
    int is32 = s32s;
    int lane = threadIdx.x & 31;
    int hs = lane & 3;
    int gw = (blockIdx.x * blockDim.x + threadIdx.x) >> 5;
    int base = gw * 64;
    if (base >= E) return;
    int cnt = min(64, E - base);

    int pe_l[2], d_l[2];
    #pragma unroll
    for (int j = 0; j < 2; j++) {
        int idx = base + j * 32 + lane;
        if (idx < E) {
            pe_l[j] = g_perm[idx];
            d_l[j] = dst_at(ei, pe_l[j], is32);
        } else { pe_l[j] = 0; d_l[j] = -1; }
    }

    const float4* keL = (const float4*)ke + lane;
    const float4* veL = (const float4*)ve + lane;

    int i1 = (1 < cnt) ? 1 : 0;
    int pa = __shfl_sync(0xffffffffu, pe_l[0], 0);
    int pb = __shfl_sync(0xffffffffu, pe_l[i1 >> 5], i1 & 31);
    float4 k0 = __ldg(keL + (size_t)pa * 32), v0 = __ldg(veL + (size_t)pa * 32);
    float4 k1 = __ldg(keL + (size_t)pb * 32), v1 = __ldg(veL + (size_t)pb * 32);

    float4 wt0, wt1, wt2, wt3;
    wt0 = wt1 = wt2 = wt3 = make_float4(0.f, 0.f, 0.f, 0.f);
    float c_h = 0.f;
    float4 a0 = make_float4(0.f, 0.f, 0.f, 0.f), a1 = a0, a2 = a0, a3 = a0;
    float aden = 0.f;
    int prevd = -1;

    #define LOADWT(dd) do { \
        const float4* bw = (const float4*)(g_wt + (size_t)(dd) * 512) + lane; \
        wt0 = __ldg(bw); wt1 = __ldg(bw + 32); wt2 = __ldg(bw + 64); wt3 = __ldg(bw + 96); \
        c_h = __ldg(&g_c[(dd) * 4 + hs]); \
    } while (0)

    #define FLUSHSEG(dd) do { \
        float* S = g_S + (size_t)(dd) * 512 + lane * 4; \
        atomicAdd(S + 0,   a0.x); atomicAdd(S + 1,   a0.y); atomicAdd(S + 2,   a0.z); atomicAdd(S + 3,   a0.w); \
        atomicAdd(S + 128, a1.x); atomicAdd(S + 129, a1.y); atomicAdd(S + 130, a1.z); atomicAdd(S + 131, a1.w); \
        atomicAdd(S + 256, a2.x); atomicAdd(S + 257, a2.y); atomicAdd(S + 258, a2.z); atomicAdd(S + 259, a2.w); \
        atomicAdd(S + 384, a3.x); atomicAdd(S + 385, a3.y); atomicAdd(S + 386, a3.z); atomicAdd(S + 387, a3.w); \
        if (lane < 4) atomicAdd(&g_den[(dd) * 4 + lane], aden); \
        a0 = a1 = a2 = a3 = make_float4(0.f, 0.f, 0.f, 0.f); \
        aden = 0.f; \
    } while (0)

    #define DOTS(K, r0, r1, r2, r3) do { \
        r0 = K.x * wt0.x + K.y * wt0.y + K.z * wt0.z + K.w * wt0.w; \
        r1 = K.x * wt1.x + K.y * wt1.y + K.z * wt1.z + K.w * wt1.w; \
        r2 = K.x * wt2.x + K.y * wt2.y + K.z * wt2.z + K.w * wt2.w; \
        r3 = K.x * wt3.x + K.y * wt3.y + K.z * wt3.z + K.w * wt3.w; \
    } while (0)

    #define ACCUM(EV, V) do { \
        a0.x += EV.x * V.x; a0.y += EV.x * V.y; a0.z += EV.x * V.z; a0.w += EV.x * V.w; \
        a1.x += EV.y * V.x; a1.y += EV.y * V.y; a1.z += EV.y * V.z; a1.w += EV.y * V.w; \
        a2.x += EV.z * V.x; a2.y += EV.z * V.y; a2.z += EV.z * V.z; a2.w += EV.z * V.w; \
        a3.x += EV.w * V.x; a3.y += EV.w * V.y; a3.z += EV.w * V.z; a3.w += EV.w * V.w; \
        aden += (hs == 0) ? EV.x : (hs == 1) ? EV.y : (hs == 2) ? EV.z : EV.w; \
    } while (0)

    int i = 0;
    for (; i + 1 < cnt; i += 2) {
        int inx2 = (i + 2 < cnt) ? i + 2 : i;
        int inx3 = (i + 3 < cnt) ? i + 3 : inx2;
        int pn2 = __shfl_sync(0xffffffffu, pe_l[inx2 >> 5], inx2 & 31);
        int pn3 = __shfl_sync(0xffffffffu, pe_l[inx3 >> 5], inx3 & 31);
        float4 k2 = __ldg(keL + (size_t)pn2 * 32);
        float4 v2 = __ldg(veL + (size_t)pn2 * 32);
        float4 k3 = __ldg(keL + (size_t)pn3 * 32);
        float4 v3 = __ldg(veL + (size_t)pn3 * 32);

        int d0 = __shfl_sync(0xffffffffu, d_l[i >> 5], i & 31);
        int d1 = __shfl_sync(0xffffffffu, d_l[(i + 1) >> 5], (i + 1) & 31);

        if (d0 != prevd) {
            if (prevd >= 0) FLUSHSEG(prevd);
            LOADWT(d0);
            prevd = d0;
        }
        float q0, q1, q2, q3;
        DOTS(k0, q0, q1, q2, q3);
        if (d1 == d0) {
            float p0, p1, p2, p3;
            DOTS(k1, p0, p1, p2, p3);
            float4 eA = score4(q0, q1, q2, q3, lane, c_h);
            float4 eB = score4(p0, p1, p2, p3, lane, c_h);
            ACCUM(eA, v0);
            ACCUM(eB, v1);
        } else {
            float4 eA = score4(q0, q1, q2, q3, lane, c_h);
            ACCUM(eA, v0);
            FLUSHSEG(prevd);
            LOADWT(d1);
            prevd = d1;
            float p0, p1, p2, p3;
            DOTS(k1, p0, p1, p2, p3);
            float4 eB = score4(p0, p1, p2, p3, lane, c_h);
            ACCUM(eB, v1);
        }
        k0 = k2; v0 = v2; k1 = k3; v1 = v3;
    }
    if (i < cnt) {
        int d0 = __shfl_sync(0xffffffffu, d_l[i >> 5], i & 31);
        if (d0 != prevd) {
            if (prevd >= 0) FLUSHSEG(prevd);
            LOADWT(d0);
            prevd = d0;
        }
        float q0, q1, q2, q3;
        DOTS(k0, q0, q1, q2, q3);
        float4 eA = score4(q0, q1, q2, q3, lane, c_h);
        ACCUM(eA, v0);
    }
    FLUSHSEG(prevd);
    #undef LOADWT
    #undef FLUSHSEG
    #undef DOTS
    #undef ACCUM
}

// ---------------- launch 4: k_post — 16-node tiles; agg=(S@Wv)/den+bv; out=agg@Wo+bo ----------------
__global__ __launch_bounds__(256) void k_post(const float* __restrict__ Wv,
                                              const float* __restrict__ bv,
                                              const float* __restrict__ Wo,
                                              const float* __restrict__ bo,
                                              float* __restrict__ Y, int n) {
    extern __shared__ float sq[];
    float* Ss = sq;               // [16][4][136] = 8704 floats
    float* As = sq + 16 * 544;    // [16][132]
    int tid = threadIdx.x;
    int row0 = blockIdx.x * 16;

    for (int i = tid; i < 16 * 512; i += 256) {
        int nl = i >> 9, rest = i & 511;
        int h = rest >> 7, d = rest & 127;
        int gr = row0 + nl;
        float v = 0.f;
        if (gr < n) {
            size_t idx = (size_t)gr * 512 + rest;
            v = g_S[idx];
            g_S[idx] = 0.f;
        }
        Ss[nl * 544 + h * 136 + d] = v;
    }
    __syncthreads();

    int cg = (tid & 31) * 4, rg = (tid >> 5) * 2;
    int h = cg >> 5;
    {
        float acc[2][4] = {};
        #pragma unroll 8
        for (int d = 0; d < DIM; d++) {
            float4 wv = __ldg((const float4*)&Wv[d * DIM + cg]);
            float a0 = Ss[(rg + 0) * 544 + h * 136 + d];
            float a1 = Ss[(rg + 1) * 544 + h * 136 + d];
            acc[0][0] += a0 * wv.x; acc[0][1] += a0 * wv.y; acc[0][2] += a0 * wv.z; acc[0][3] += a0 * wv.w;
            acc[1][0] += a1 * wv.x; acc[1][1] += a1 * wv.y; acc[1][2] += a1 * wv.z; acc[1][3] += a1 * wv.w;
        }
        float4 bb = __ldg((const float4*)&bv[cg]);
        #pragma unroll
        for (int rr = 0; rr < 2; rr++) {
            int gr = row0 + rg + rr;
            float4 o = make_float4(0.f, 0.f, 0.f, 0.f);
            if (gr < n) {
                float den = g_den[gr * HEADS + h];
                if (den > 0.f) {
                    float inv = 1.f / den;
                    o = make_float4(acc[rr][0] * inv + bb.x, acc[rr][1] * inv + bb.y,
                                    acc[rr][2] * inv + bb.z, acc[rr][3] * inv + bb.w);
                }
            }
            As[(rg + rr) * 132 + cg + 0] = o.x;
            As[(rg + rr) * 132 + cg + 1] = o.y;
            As[(rg + rr) * 132 + cg + 2] = o.z;
            As[(rg + rr) * 132 + cg + 3] = o.w;
        }
    }
    __syncthreads();

    if (tid < 64) {
        int gr = row0 + (tid >> 2);
        if (gr < n) g_den[gr * HEADS + (tid & 3)] = 0.f;
    }

    {
        float acc[2][4] = {};
        #pragma unroll 8
        for (int d = 0; d < DIM; d++) {
            float4 w = __ldg((const float4*)&Wo[d * DIM + cg]);
            float a0 = As[(rg + 0) * 132 + d];
            float a1 = As[(rg + 1) * 132 + d];
            acc[0][0] += a0 * w.x; acc[0][1] += a0 * w.y; acc[0][2] += a0 * w.z; acc[0][3] += a0 * w.w;
            acc[1][0] += a1 * w.x; acc[1][1] += a1 * w.y; acc[1][2] += a1 * w.z; acc[1][3] += a1 * w.w;
        }
        float4 bb = __ldg((const float4*)&bo[cg]);
        #pragma unroll
        for (int rr = 0; rr < 2; rr++) {
            int gr = row0 + rg + rr;
            if (gr < n) {
                float4 o = make_float4(acc[rr][0] + bb.x, acc[rr][1] + bb.y,
                                       acc[rr][2] + bb.z, acc[rr][3] + bb.w);
                *(float4*)&Y[gr * DIM + cg] = o;
            }
        }
    }
}

extern "C" void kernel_launch(void* const* d_in, const int* in_sizes, int n_in,
                              void* d_out, int out_size) {
    const float* q_nodes = (const float*)d_in[0];
    const float* k_edges = (const float*)d_in[1];
    const float* v_edges = (const float*)d_in[2];
    const float* Wq = (const float*)d_in[3];
    const float* bq = (const float*)d_in[4];
    const float* Wk = (const float*)d_in[5];
    const float* bk = (const float*)d_in[6];
    const float* Wv = (const float*)d_in[7];
    const float* bv = (const float*)d_in[8];
    const float* Wo = (const float*)d_in[9];
    const float* bo = (const float*)d_in[10];
    const void*  ei = (const void*)d_in[11];

    int N = in_sizes[0] / DIM;
    int E = in_sizes[1] / DIM;

    const int smem_ws   = 32 * 132 * (int)sizeof(float);              // 16896
    const int smem_post = (16 * 544 + 16 * 132) * (int)sizeof(float); // 43264
    cudaFuncSetAttribute(k_wt_scatter, cudaFuncAttributeMaxDynamicSharedMemorySize, smem_ws);
    cudaFuncSetAttribute(k_post, cudaFuncAttributeMaxDynamicSharedMemorySize, smem_post);

    int histBlocks = (E + 255) / 256;
    int wtBlocks = ((N + 31) / 32) * 4;
    int postBlocks = (N + 15) / 16;
    int ewarps = (E + 63) / 64;
    int eblocks = (ewarps + 7) / 8;

    k_hist_prep<<<32 + histBlocks, 256>>>(Wq, bq, Wk, bk, ei, E);                        // 0
    k_scan<<<1, 1024>>>(N);                                                              // 1
    k_wt_scatter<<<wtBlocks + histBlocks, 256, smem_ws>>>(q_nodes, ei, N, E, wtBlocks);  // 2
    k_edge<<<eblocks, 256>>>(k_edges, v_edges, ei, E);                                   // 3 (profiled)
    k_post<<<postBlocks, 256, smem_post>>>(Wv, bv, Wo, bo, (float*)d_out, N);            // 4
}

// round 16
// speedup vs baseline: 1.2602x; 1.0308x over previous
#include <cuda_runtime.h>
#include <cstdint>
#include <math.h>

#define N_NODES 10000
#define E_EDGES 640000
#define DIM     128
#define HEADS   4

// device globals zero-init at load; consumers re-zero what they read.
__device__ float g_M[128 * 512];         // M[c][h*128+k], scale folded
__device__ float g_B[512];               // B[h*128+k], scale folded
__device__ float g_Mb[128 * 4];          // Mb[c][h], scale folded
__device__ float g_cb[4];                // scale folded
__device__ float g_wt[N_NODES * 512];    // w-tilde [n][h*128+k]
__device__ float g_c[N_NODES * HEADS];
__device__ float g_S[N_NODES * 512];     // self-cleaned by k_post
__device__ float g_den[N_NODES * HEADS]; // self-cleaned by k_post
__device__ int   g_cnt[N_NODES];         // self-cleaned by k_scan
__device__ int   g_cur[N_NODES];         // fully rewritten by k_scan
__device__ int   g_perm[E_EDGES];        // fully rewritten by scatter

__device__ __forceinline__ int detect32(const void* ei) {
    const long long* p = (const long long*)ei;
    long long x = 0;
    #pragma unroll
    for (int i = 0; i < 8; i++) x |= p[i];
    return (((unsigned long long)x) >> 32) != 0ull;
}
__device__ __forceinline__ int dst_at(const void* ei, int e, int is32) {
    return is32 ? ((const int*)ei)[e] : (int)((const long long*)ei)[e];
}

// ---------------- stream A: k_prep — build M, B, Mb, cb (32 blocks) ----------------
__global__ __launch_bounds__(256) void k_prep(const float* __restrict__ Wq,
                                              const float* __restrict__ bq,
                                              const float* __restrict__ Wk,
                                              const float* __restrict__ bk) {
    const float scale = 0.17677669529663689f;  // 1/sqrt(32)
    int tid = threadIdx.x;
    int b = blockIdx.x;
    int c = tid & 127, kp = tid >> 7;
    #pragma unroll
    for (int h = 0; h < 4; h++) {
        float wq[32];
        #pragma unroll
        for (int d4 = 0; d4 < 8; d4++) {
            float4 v = __ldg((const float4*)&Wq[c * 128 + h * 32 + d4 * 4]);
            wq[d4 * 4 + 0] = v.x; wq[d4 * 4 + 1] = v.y;
            wq[d4 * 4 + 2] = v.z; wq[d4 * 4 + 3] = v.w;
        }
        #pragma unroll
        for (int j = 0; j < 2; j++) {
            int kl = 2 * kp + j;
            float s = 0.f;
            #pragma unroll
            for (int d = 0; d < 32; d++)
                s += wq[d] * __ldg(&Wk[(b * 4 + kl) * 128 + h * 32 + d]);
            g_M[c * 512 + h * 128 + b * 4 + kl] = s * scale;
        }
    }
    if (tid < 16) {
        int kl = tid >> 2, h = tid & 3;
        float s = 0.f;
        #pragma unroll
        for (int d = 0; d < 32; d++)
            s += __ldg(&bq[h * 32 + d]) * __ldg(&Wk[(b * 4 + kl) * 128 + h * 32 + d]);
        g_B[h * 128 + b * 4 + kl] = s * scale;
    }
    if (b == 0) {
        int hp = tid >> 7;
        #pragma unroll
        for (int j = 0; j < 2; j++) {
            int h = 2 * hp + j;
            float s = 0.f;
            #pragma unroll
            for (int d = 0; d < 32; d++)
                s += __ldg(&Wq[c * 128 + h * 32 + d]) * __ldg(&bk[h * 32 + d]);
            g_Mb[c * 4 + h] = s * scale;
        }
        if (tid < 4) {
            float s = 0.f;
            #pragma unroll
            for (int d = 0; d < 32; d++) s += __ldg(&bq[tid * 32 + d]) * __ldg(&bk[tid * 32 + d]);
            g_cb[tid] = s * scale;
        }
    }
}

// ---------------- stream B: k_hist ----------------
__global__ void k_hist(const void* __restrict__ ei, int E) {
    __shared__ int s32;
    if (threadIdx.x == 0) s32 = detect32(ei);
    __syncthreads();
    int e = blockIdx.x * blockDim.x + threadIdx.x;
    if (e < E) atomicAdd(&g_cnt[dst_at(ei, e, s32)], 1);
}

// ---------------- stream A: k_wt — wt = X@M + B (32-row tiles, 4 col slices) ----------------
__global__ __launch_bounds__(256) void k_wt(const float* __restrict__ X, int n) {
    extern __shared__ float sv[];
    float* As = sv;               // [32][132]
    int tid = threadIdx.x;
    int b = blockIdx.x;
    int row0 = (b >> 2) * 32;
    int by = b & 3;

    for (int i = tid; i < 32 * DIM; i += 256) {
        int r = i >> 7, c = i & 127;
        int gr = row0 + r;
        As[r * 132 + c] = (gr < n) ? X[gr * DIM + c] : 0.f;
    }
    __syncthreads();

    int cg = (tid & 31) * 4, rg = (tid >> 5) * 4;
    float acc[4][4] = {};
    #pragma unroll 8
    for (int d = 0; d < DIM; d++) {
        float4 w = __ldg((const float4*)&g_M[d * 512 + by * 128 + cg]);
        #pragma unroll
        for (int rr = 0; rr < 4; rr++) {
            float a = As[(rg + rr) * 132 + d];
            acc[rr][0] += a * w.x; acc[rr][1] += a * w.y;
            acc[rr][2] += a * w.z; acc[rr][3] += a * w.w;
        }
    }
    float4 bb = __ldg((const float4*)&g_B[by * 128 + cg]);
    #pragma unroll
    for (int rr = 0; rr < 4; rr++) {
        int gr = row0 + rg + rr;
        if (gr < n) {
            float4 o = make_float4(acc[rr][0] + bb.x, acc[rr][1] + bb.y,
                                   acc[rr][2] + bb.z, acc[rr][3] + bb.w);
            *(float4*)&g_wt[(size_t)gr * 512 + by * 128 + cg] = o;
        }
    }
    if (by == 0 && tid < 128) {
        int nl = tid >> 2, h = tid & 3;
        int node = row0 + nl;
        float s = 0.f;
        #pragma unroll 8
        for (int c = 0; c < 128; c++) s += As[nl * 132 + c] * __ldg(&g_Mb[c * 4 + h]);
        if (node < n) g_c[node * 4 + h] = s + g_cb[h];
    }
}

// ---------------- stream B: scan (+ self-clean g_cnt) ----------------
__global__ __launch_bounds__(1024) void k_scan(int n) {
    __shared__ int ws[32];
    int t = threadIdx.x, lane = t & 31, wd = t >> 5;
    int per = (n + 1023) / 1024;
    int base = t * per;
    int s = 0;
    for (int i = 0; i < per; i++) {
        int idx = base + i;
        if (idx < n) s += g_cnt[idx];
    }
    int incl = s;
    #pragma unroll
    for (int off = 1; off < 32; off <<= 1) {
        int y = __shfl_up_sync(0xffffffffu, incl, off);
        if (lane >= off) incl += y;
    }
    if (lane == 31) ws[wd] = incl;
    __syncthreads();
    if (wd == 0) {
        int v = ws[lane];
        int iv = v;
        #pragma unroll
        for (int off = 1; off < 32; off <<= 1) {
            int y = __shfl_up_sync(0xffffffffu, iv, off);
            if (lane >= off) iv += y;
        }
        ws[lane] = iv - v;
    }
    __syncthreads();
    int run = ws[wd] + incl - s;
    for (int i = 0; i < per; i++) {
        int idx = base + i;
        if (idx < n) {
            int v = g_cnt[idx];
            g_cur[idx] = run;
            run += v;
            g_cnt[idx] = 0;
        }
    }
}

// ---------------- stream B: scatter ----------------
__global__ void k_scatter(const void* __restrict__ ei, int E) {
    __shared__ int s32;
    if (threadIdx.x == 0) s32 = detect32(ei);
    __syncthreads();
    int e = blockIdx.x * blockDim.x + threadIdx.x;
    if (e < E) {
        int pos = atomicAdd(&g_cur[dst_at(ei, e, s32)], 1);
        g_perm[pos] = e;
    }
}

// ---------------- k_edge helpers ----------------
__device__ __forceinline__ float4 score4(float q0, float q1, float q2, float q3,
                                         int lane, float c_h) {
    float ta = (lane & 1) ? q0 : q1;
    float ra = __shfl_xor_sync(0xffffffffu, ta, 1);
    float fa = ((lane & 1) ? q1 : q0) + ra;
    float tb = (lane & 1) ? q2 : q3;
    float rb = __shfl_xor_sync(0xffffffffu, tb, 1);
    float fb = ((lane & 1) ? q3 : q2) + rb;
    float tc = (lane & 2) ? fa : fb;
    float rc = __shfl_xor_sync(0xffffffffu, tc, 2);
    float fc = ((lane & 2) ? fb : fa) + rc;
    fc += __shfl_xor_sync(0xffffffffu, fc, 4);
    fc += __shfl_xor_sync(0xffffffffu, fc, 8);
    fc += __shfl_xor_sync(0xffffffffu, fc, 16);
    float e = __expf(fc + c_h);
    float s1 = __shfl_xor_sync(0xffffffffu, e, 1);
    float e_even = (lane & 1) ? s1 : e;
    float e_odd  = (lane & 1) ? e : s1;
    float s2e = __shfl_xor_sync(0xffffffffu, e_even, 2);
    float s2o = __shfl_xor_sync(0xffffffffu, e_odd, 2);
    float4 r;
    r.x = (lane & 2) ? s2e : e_even;
    r.z = (lane & 2) ? e_even : s2e;
    r.y = (lane & 2) ? s2o : e_odd;
    r.w = (lane & 2) ? e_odd : s2o;
    return r;
}

// ---------------- joined: k_edge — pairwise-interleaved score chains ----------------
__global__ __launch_bounds__(256, 3) void k_edge(const float* __restrict__ ke,
                                                 const float* __restrict__ ve,
                                                 const void* __restrict__ ei, int E) {
    __shared__ int s32s;
    if (threadIdx.x == 0) s32s = detect32(ei);
    __syncthreads();
    int is32 = s32s;
    int lane = threadIdx.x & 31;
    int hs = lane & 3;
    int gw = (blockIdx.x * blockDim.x + threadIdx.x) >> 5;
    int base = gw * 64;
    if (base >= E) return;
    int cnt = min(64, E - base);

    int pe_l[2], d_l[2];
    #pragma unroll
    for (int j = 0; j < 2; j++) {
        int idx = base + j * 32 + lane;
        if (idx < E) {
            pe_l[j] = g_perm[idx];
            d_l[j] = dst_at(ei, pe_l[j], is32);
        } else { pe_l[j] = 0; d_l[j] = -1; }
    }

    const float4* keL = (const float4*)ke + lane;
    const float4* veL = (const float4*)ve + lane;

    int i1 = (1 < cnt) ? 1 : 0;
    int pa = __shfl_sync(0xffffffffu, pe_l[0], 0);
    int pb = __shfl_sync(0xffffffffu, pe_l[i1 >> 5], i1 & 31);
    float4 k0 = __ldg(keL + (size_t)pa * 32), v0 = __ldg(veL + (size_t)pa * 32);
    float4 k1 = __ldg(keL + (size_t)pb * 32), v1 = __ldg(veL + (size_t)pb * 32);

    float4 wt0, wt1, wt2, wt3;
    wt0 = wt1 = wt2 = wt3 = make_float4(0.f, 0.f, 0.f, 0.f);
    float c_h = 0.f;
    float4 a0 = make_float4(0.f, 0.f, 0.f, 0.f), a1 = a0, a2 = a0, a3 = a0;
    float aden = 0.f;
    int prevd = -1;

    #define LOADWT(dd) do { \
        const float4* bw = (const float4*)(g_wt + (size_t)(dd) * 512) + lane; \
        wt0 = __ldg(bw); wt1 = __ldg(bw + 32); wt2 = __ldg(bw + 64); wt3 = __ldg(bw + 96); \
        c_h = __ldg(&g_c[(dd) * 4 + hs]); \
    } while (0)

    #define FLUSHSEG(dd) do { \
        float* S = g_S + (size_t)(dd) * 512 + lane * 4; \
        atomicAdd(S + 0,   a0.x); atomicAdd(S + 1,   a0.y); atomicAdd(S + 2,   a0.z); atomicAdd(S + 3,   a0.w); \
        atomicAdd(S + 128, a1.x); atomicAdd(S + 129, a1.y); atomicAdd(S + 130, a1.z); atomicAdd(S + 131, a1.w); \
        atomicAdd(S + 256, a2.x); atomicAdd(S + 257, a2.y); atomicAdd(S + 258, a2.z); atomicAdd(S + 259, a2.w); \
        atomicAdd(S + 384, a3.x); atomicAdd(S + 385, a3.y); atomicAdd(S + 386, a3.z); atomicAdd(S + 387, a3.w); \
        if (lane < 4) atomicAdd(&g_den[(dd) * 4 + lane], aden); \
        a0 = a1 = a2 = a3 = make_float4(0.f, 0.f, 0.f, 0.f); \
        aden = 0.f; \
    } while (0)

    #define DOTS(K, r0, r1, r2, r3) do { \
        r0 = K.x * wt0.x + K.y * wt0.y + K.z * wt0.z + K.w * wt0.w; \
        r1 = K.x * wt1.x + K.y * wt1.y + K.z * wt1.z + K.w * wt1.w; \
        r2 = K.x * wt2.x + K.y * wt2.y + K.z * wt2.z + K.w * wt2.w; \
        r3 = K.x * wt3.x + K.y * wt3.y + K.z * wt3.z + K.w * wt3.w; \
    } while (0)

    #define ACCUM(EV, V) do { \
        a0.x += EV.x * V.x; a0.y += EV.x * V.y; a0.z += EV.x * V.z; a0.w += EV.x * V.w; \
        a1.x += EV.y * V.x; a1.y += EV.y * V.y; a1.z += EV.y * V.z; a1.w += EV.y * V.w; \
        a2.x += EV.z * V.x; a2.y += EV.z * V.y; a2.z += EV.z * V.z; a2.w += EV.z * V.w; \
        a3.x += EV.w * V.x; a3.y += EV.w * V.y; a3.z += EV.w * V.z; a3.w += EV.w * V.w; \
        aden += (hs == 0) ? EV.x : (hs == 1) ? EV.y : (hs == 2) ? EV.z : EV.w; \
    } while (0)

    int i = 0;
    for (; i + 1 < cnt; i += 2) {
        int inx2 = (i + 2 < cnt) ? i + 2 : i;
        int inx3 = (i + 3 < cnt) ? i + 3 : inx2;
        int pn2 = __shfl_sync(0xffffffffu, pe_l[inx2 >> 5], inx2 & 31);
        int pn3 = __shfl_sync(0xffffffffu, pe_l[inx3 >> 5], inx3 & 31);
        float4 k2 = __ldg(keL + (size_t)pn2 * 32);
        float4 v2 = __ldg(veL + (size_t)pn2 * 32);
        float4 k3 = __ldg(keL + (size_t)pn3 * 32);
        float4 v3 = __ldg(veL + (size_t)pn3 * 32);

        int d0 = __shfl_sync(0xffffffffu, d_l[i >> 5], i & 31);
        int d1 = __shfl_sync(0xffffffffu, d_l[(i + 1) >> 5], (i + 1) & 31);

        if (d0 != prevd) {
            if (prevd >= 0) FLUSHSEG(prevd);
            LOADWT(d0);
            prevd = d0;
        }
        float q0, q1, q2, q3;
        DOTS(k0, q0, q1, q2, q3);
        if (d1 == d0) {
            float p0, p1, p2, p3;
            DOTS(k1, p0, p1, p2, p3);
            float4 eA = score4(q0, q1, q2, q3, lane, c_h);
            float4 eB = score4(p0, p1, p2, p3, lane, c_h);
            ACCUM(eA, v0);
            ACCUM(eB, v1);
        } else {
            float4 eA = score4(q0, q1, q2, q3, lane, c_h);
            ACCUM(eA, v0);
            FLUSHSEG(prevd);
            LOADWT(d1);
            prevd = d1;
            float p0, p1, p2, p3;
            DOTS(k1, p0, p1, p2, p3);
            float4 eB = score4(p0, p1, p2, p3, lane, c_h);
            ACCUM(eB, v1);
        }
        k0 = k2; v0 = v2; k1 = k3; v1 = v3;
    }
    if (i < cnt) {
        int d0 = __shfl_sync(0xffffffffu, d_l[i >> 5], i & 31);
        if (d0 != prevd) {
            if (prevd >= 0) FLUSHSEG(prevd);
            LOADWT(d0);
            prevd = d0;
        }
        float q0, q1, q2, q3;
        DOTS(k0, q0, q1, q2, q3);
        float4 eA = score4(q0, q1, q2, q3, lane, c_h);
        ACCUM(eA, v0);
    }
    FLUSHSEG(prevd);
    #undef LOADWT
    #undef FLUSHSEG
    #undef DOTS
    #undef ACCUM
}

// ---------------- k_post — 16-node tiles; agg=(S@Wv)/den+bv; out=agg@Wo+bo ----------------
__global__ __launch_bounds__(256) void k_post(const float* __restrict__ Wv,
                                              const float* __restrict__ bv,
                                              const float* __restrict__ Wo,
                                              const float* __restrict__ bo,
                                              float* __restrict__ Y, int n) {
    extern __shared__ float sq[];
    float* Ss = sq;               // [16][4][136]
    float* As = sq + 16 * 544;    // [16][132]
    int tid = threadIdx.x;
    int row0 = blockIdx.x * 16;

    for (int i = tid; i < 16 * 512; i += 256) {
        int nl = i >> 9, rest = i & 511;
        int h = rest >> 7, d = rest & 127;
        int gr = row0 + nl;
        float v = 0.f;
        if (gr < n) {
            size_t idx = (size_t)gr * 512 + rest;
            v = g_S[idx];
            g_S[idx] = 0.f;
        }
        Ss[nl * 544 + h * 136 + d] = v;
    }
    __syncthreads();

    int cg = (tid & 31) * 4, rg = (tid >> 5) * 2;
    int h = cg >> 5;
    {
        float acc[2][4] = {};
        #pragma unroll 8
        for (int d = 0; d < DIM; d++) {
            float4 wv = __ldg((const float4*)&Wv[d * DIM + cg]);
            float a0 = Ss[(rg + 0) * 544 + h * 136 + d];
            float a1 = Ss[(rg + 1) * 544 + h * 136 + d];
            acc[0][0] += a0 * wv.x; acc[0][1] += a0 * wv.y; acc[0][2] += a0 * wv.z; acc[0][3] += a0 * wv.w;
            acc[1][0] += a1 * wv.x; acc[1][1] += a1 * wv.y; acc[1][2] += a1 * wv.z; acc[1][3] += a1 * wv.w;
        }
        float4 bb = __ldg((const float4*)&bv[cg]);
        #pragma unroll
        for (int rr = 0; rr < 2; rr++) {
            int gr = row0 + rg + rr;
            float4 o = make_float4(0.f, 0.f, 0.f, 0.f);
            if (gr < n) {
                float den = g_den[gr * HEADS + h];
                if (den > 0.f) {
                    float inv = 1.f / den;
                    o = make_float4(acc[rr][0] * inv + bb.x, acc[rr][1] * inv + bb.y,
                                    acc[rr][2] * inv + bb.z, acc[rr][3] * inv + bb.w);
                }
            }
            As[(rg + rr) * 132 + cg + 0] = o.x;
            As[(rg + rr) * 132 + cg + 1] = o.y;
            As[(rg + rr) * 132 + cg + 2] = o.z;
            As[(rg + rr) * 132 + cg + 3] = o.w;
        }
    }
    __syncthreads();

    if (tid < 64) {
        int gr = row0 + (tid >> 2);
        if (gr < n) g_den[gr * HEADS + (tid & 3)] = 0.f;
    }

    {
        float acc[2][4] = {};
        #pragma unroll 8
        for (int d = 0; d < DIM; d++) {
            float4 w = __ldg((const float4*)&Wo[d * DIM + cg]);
            float a0 = As[(rg + 0) * 132 + d];
            float a1 = As[(rg + 1) * 132 + d];
            acc[0][0] += a0 * w.x; acc[0][1] += a0 * w.y; acc[0][2] += a0 * w.z; acc[0][3] += a0 * w.w;
            acc[1][0] += a1 * w.x; acc[1][1] += a1 * w.y; acc[1][2] += a1 * w.z; acc[1][3] += a1 * w.w;
        }
        float4 bb = __ldg((const float4*)&bo[cg]);
        #pragma unroll
        for (int rr = 0; rr < 2; rr++) {
            int gr = row0 + rg + rr;
            if (gr < n) {
                float4 o = make_float4(acc[rr][0] + bb.x, acc[rr][1] + bb.y,
                                       acc[rr][2] + bb.z, acc[rr][3] + bb.w);
                *(float4*)&Y[gr * DIM + cg] = o;
            }
        }
    }
}

extern "C" void kernel_launch(void* const* d_in, const int* in_sizes, int n_in,
                              void* d_out, int out_size) {
    const float* q_nodes = (const float*)d_in[0];
    const float* k_edges = (const float*)d_in[1];
    const float* v_edges = (const float*)d_in[2];
    const float* Wq = (const float*)d_in[3];
    const float* bq = (const float*)d_in[4];
    const float* Wk = (const float*)d_in[5];
    const float* bk = (const float*)d_in[6];
    const float* Wv = (const float*)d_in[7];
    const float* bv = (const float*)d_in[8];
    const float* Wo = (const float*)d_in[9];
    const float* bo = (const float*)d_in[10];
    const void*  ei = (const void*)d_in[11];

    int N = in_sizes[0] / DIM;
    int E = in_sizes[1] / DIM;

    // lazily created host-side objects (no device memory involved)
    static cudaStream_t sA = nullptr, sB = nullptr;
    static cudaEvent_t evRoot = nullptr, evA = nullptr, evB = nullptr;
    if (sA == nullptr) {
        cudaStreamCreateWithFlags(&sA, cudaStreamNonBlocking);
        cudaStreamCreateWithFlags(&sB, cudaStreamNonBlocking);
        cudaEventCreateWithFlags(&evRoot, cudaEventDisableTiming);
        cudaEventCreateWithFlags(&evA, cudaEventDisableTiming);
        cudaEventCreateWithFlags(&evB, cudaEventDisableTiming);
    }

    const int smem_ws   = 32 * 132 * (int)sizeof(float);              // 16896
    const int smem_post = (16 * 544 + 16 * 132) * (int)sizeof(float); // 43264
    cudaFuncSetAttribute(k_wt, cudaFuncAttributeMaxDynamicSharedMemorySize, smem_ws);
    cudaFuncSetAttribute(k_post, cudaFuncAttributeMaxDynamicSharedMemorySize, smem_post);

    int histBlocks = (E + 255) / 256;
    int wtBlocks = ((N + 31) / 32) * 4;
    int postBlocks = (N + 15) / 16;
    int ewarps = (E + 63) / 64;
    int eblocks = (ewarps + 7) / 8;

    // fork: stream A = prep -> wt ; stream B = hist -> scan -> scatter
    cudaEventRecord(evRoot, 0);
    cudaStreamWaitEvent(sA, evRoot, 0);
    cudaStreamWaitEvent(sB, evRoot, 0);

    k_prep<<<32, 256, 0, sA>>>(Wq, bq, Wk, bk);
    k_hist<<<histBlocks, 256, 0, sB>>>(ei, E);
    k_wt<<<wtBlocks, 256, smem_ws, sA>>>(q_nodes, N);
    k_scan<<<1, 1024, 0, sB>>>(N);
    k_scatter<<<histBlocks, 256, 0, sB>>>(ei, E);

    cudaEventRecord(evA, sA);
    cudaEventRecord(evB, sB);
    cudaStreamWaitEvent(0, evA, 0);
    cudaStreamWaitEvent(0, evB, 0);

    k_edge<<<eblocks, 256>>>(k_edges, v_edges, ei, E);
    k_post<<<postBlocks, 256, smem_post>>>(Wv, bv, Wo, bo, (float*)d_out, N);
}

// round 17
// speedup vs baseline: 1.2759x; 1.0124x over previous
#include <cuda_runtime.h>
#include <cstdint>
#include <math.h>

#define N_NODES 10000
#define E_EDGES 640000
#define DIM     128
#define HEADS   4

__device__ float g_M[128 * 512];
__device__ float g_B[512];
__device__ float g_Mb[128 * 4];
__device__ float g_cb[4];
__device__ float g_wt[N_NODES * 512];
__device__ float g_c[N_NODES * HEADS];
__device__ float g_S[N_NODES * 512];     // self-cleaned by k_post
__device__ float g_den[N_NODES * HEADS]; // self-cleaned by k_post
__device__ int   g_cnt[N_NODES];         // self-cleaned by scan phase
__device__ int   g_cur[N_NODES];
__device__ int   g_perm[E_EDGES];
__device__ unsigned g_barCnt = 0;
__device__ unsigned g_barGen = 0;

__device__ __forceinline__ int detect32(const void* ei) {
    const long long* p = (const long long*)ei;
    long long x = 0;
    #pragma unroll
    for (int i = 0; i < 8; i++) x |= p[i];
    return (((unsigned long long)x) >> 32) != 0ull;
}
__device__ __forceinline__ int dst_at(const void* ei, int e, int is32) {
    return is32 ? ((const int*)ei)[e] : (int)((const long long*)ei)[e];
}

// all-resident grid barrier (sense-reversal via generation counter)
__device__ __forceinline__ void gridbar(unsigned nb) {
    __threadfence();
    __syncthreads();
    if (threadIdx.x == 0) {
        unsigned gen = *((volatile unsigned*)&g_barGen);
        unsigned t = atomicAdd(&g_barCnt, 1u);
        if (t == nb - 1) {
            g_barCnt = 0u;
            __threadfence();
            atomicAdd(&g_barGen, 1u);
        } else {
            while (*((volatile unsigned*)&g_barGen) == gen) { __nanosleep(64); }
        }
    }
    __syncthreads();
}

// ---------------- launch 0: hist ----------------
__global__ void k_hist(const void* __restrict__ ei, int E) {
    __shared__ int s32;
    if (threadIdx.x == 0) s32 = detect32(ei);
    __syncthreads();
    int e = blockIdx.x * blockDim.x + threadIdx.x;
    if (e < E) atomicAdd(&g_cnt[dst_at(ei, e, s32)], 1);
}

// ---------------- launch 1: k_node — fused prep|scan -> barrier -> scatter|wt ----------------
#define SCATB 80
__global__ __launch_bounds__(256, 2) void k_node(const float* __restrict__ X,
                                                 const float* __restrict__ Wq,
                                                 const float* __restrict__ bq,
                                                 const float* __restrict__ Wk,
                                                 const float* __restrict__ bk,
                                                 const void* __restrict__ ei,
                                                 int n, int E, int nb) {
    extern __shared__ float sv[];
    const float scale = 0.17677669529663689f;  // 1/sqrt(32)
    int tid = threadIdx.x;
    int b = blockIdx.x;

    // ---- phase 1 ----
    if (b < 32) {
        // prep: build M, B (block b owns k in [4b,4b+4)); block 0 also Mb, cb
        int c = tid & 127, kp = tid >> 7;
        #pragma unroll
        for (int h = 0; h < 4; h++) {
            float wq[32];
            #pragma unroll
            for (int d4 = 0; d4 < 8; d4++) {
                float4 v = __ldg((const float4*)&Wq[c * 128 + h * 32 + d4 * 4]);
                wq[d4 * 4 + 0] = v.x; wq[d4 * 4 + 1] = v.y;
                wq[d4 * 4 + 2] = v.z; wq[d4 * 4 + 3] = v.w;
            }
            #pragma unroll
            for (int j = 0; j < 2; j++) {
                int kl = 2 * kp + j;
                float s = 0.f;
                #pragma unroll
                for (int d = 0; d < 32; d++)
                    s += wq[d] * __ldg(&Wk[(b * 4 + kl) * 128 + h * 32 + d]);
                g_M[c * 512 + h * 128 + b * 4 + kl] = s * scale;
            }
        }
        if (tid < 16) {
            int kl = tid >> 2, h = tid & 3;
            float s = 0.f;
            #pragma unroll
            for (int d = 0; d < 32; d++)
                s += __ldg(&bq[h * 32 + d]) * __ldg(&Wk[(b * 4 + kl) * 128 + h * 32 + d]);
            g_B[h * 128 + b * 4 + kl] = s * scale;
        }
        if (b == 0) {
            int hp = tid >> 7;
            #pragma unroll
            for (int j = 0; j < 2; j++) {
                int h = 2 * hp + j;
                float s = 0.f;
                #pragma unroll
                for (int d = 0; d < 32; d++)
                    s += __ldg(&Wq[c * 128 + h * 32 + d]) * __ldg(&bk[h * 32 + d]);
                g_Mb[c * 4 + h] = s * scale;
            }
            if (tid < 4) {
                float s = 0.f;
                #pragma unroll
                for (int d = 0; d < 32; d++)
                    s += __ldg(&bq[tid * 32 + d]) * __ldg(&bk[tid * 32 + d]);
                g_cb[tid] = s * scale;
            }
        }
    } else if (b == 32) {
        // scan (256 threads), + self-clean g_cnt
        int* ws = (int*)sv;   // 8 ints
        int lane = tid & 31, wd = tid >> 5;
        int per = (n + 255) / 256;
        int base = tid * per;
        int s = 0;
        for (int i = 0; i < per; i++) {
            int idx = base + i;
            if (idx < n) s += g_cnt[idx];
        }
        int incl = s;
        #pragma unroll
        for (int off = 1; off < 32; off <<= 1) {
            int y = __shfl_up_sync(0xffffffffu, incl, off);
            if (lane >= off) incl += y;
        }
        if (lane == 31) ws[wd] = incl;
        __syncthreads();
        if (wd == 0 && lane < 8) {
            int v = ws[lane];
            int iv = v;
            #pragma unroll
            for (int off = 1; off < 8; off <<= 1) {
                int y = __shfl_up_sync(0xffu, iv, off);
                if (lane >= off) iv += y;
            }
            ws[lane] = iv - v;
        }
        __syncthreads();
        int run = ws[wd] + incl - s;
        for (int i = 0; i < per; i++) {
            int idx = base + i;
            if (idx < n) {
                int v = g_cnt[idx];
                g_cur[idx] = run;
                run += v;
                g_cnt[idx] = 0;
            }
        }
    }

    gridbar((unsigned)nb);

    // ---- phase 2 ----
    if (b < SCATB) {
        // scatter (grid-stride over SCATB blocks)
        __shared__ int s32;
        if (tid == 0) s32 = detect32(ei);
        __syncthreads();
        int stride = SCATB * 256;
        for (int e = b * 256 + tid; e < E; e += stride) {
            int pos = atomicAdd(&g_cur[dst_at(ei, e, s32)], 1);
            g_perm[pos] = e;
        }
    } else {
        // wt tiles (grid-stride)
        float* As = sv;   // [32][132]
        int wtTiles = ((n + 31) / 32) * 4;
        for (int t = b - SCATB; t < wtTiles; t += nb - SCATB) {
            int row0 = (t >> 2) * 32;
            int by = t & 3;
            for (int i = tid; i < 32 * DIM; i += 256) {
                int r = i >> 7, c = i & 127;
                int gr = row0 + r;
                As[r * 132 + c] = (gr < n) ? X[gr * DIM + c] : 0.f;
            }
            __syncthreads();
            int cg = (tid & 31) * 4, rg = (tid >> 5) * 4;
            float acc[4][4] = {};
            #pragma unroll 8
            for (int d = 0; d < DIM; d++) {
                float4 w = __ldg((const float4*)&g_M[d * 512 + by * 128 + cg]);
                #pragma unroll
                for (int rr = 0; rr < 4; rr++) {
                    float a = As[(rg + rr) * 132 + d];
                    acc[rr][0] += a * w.x; acc[rr][1] += a * w.y;
                    acc[rr][2] += a * w.z; acc[rr][3] += a * w.w;
                }
            }
            float4 bb = __ldg((const float4*)&g_B[by * 128 + cg]);
            #pragma unroll
            for (int rr = 0; rr < 4; rr++) {
                int gr = row0 + rg + rr;
                if (gr < n) {
                    float4 o = make_float4(acc[rr][0] + bb.x, acc[rr][1] + bb.y,
                                           acc[rr][2] + bb.z, acc[rr][3] + bb.w);
                    *(float4*)&g_wt[(size_t)gr * 512 + by * 128 + cg] = o;
                }
            }
            if (by == 0 && tid < 128) {
                int nl = tid >> 2, h = tid & 3;
                int node = row0 + nl;
                float s = 0.f;
                #pragma unroll 8
                for (int c = 0; c < 128; c++) s += As[nl * 132 + c] * __ldg(&g_Mb[c * 4 + h]);
                if (node < n) g_c[node * 4 + h] = s + g_cb[h];
            }
            __syncthreads();
        }
    }
}

// ---------------- k_edge helpers ----------------
__device__ __forceinline__ float4 score4(float q0, float q1, float q2, float q3,
                                         int lane, float c_h) {
    float ta = (lane & 1) ? q0 : q1;
    float ra = __shfl_xor_sync(0xffffffffu, ta, 1);
    float fa = ((lane & 1) ? q1 : q0) + ra;
    float tb = (lane & 1) ? q2 : q3;
    float rb = __shfl_xor_sync(0xffffffffu, tb, 1);
    float fb = ((lane & 1) ? q3 : q2) + rb;
    float tc = (lane & 2) ? fa : fb;
    float rc = __shfl_xor_sync(0xffffffffu, tc, 2);
    float fc = ((lane & 2) ? fb : fa) + rc;
    fc += __shfl_xor_sync(0xffffffffu, fc, 4);
    fc += __shfl_xor_sync(0xffffffffu, fc, 8);
    fc += __shfl_xor_sync(0xffffffffu, fc, 16);
    float e = __expf(fc + c_h);
    float s1 = __shfl_xor_sync(0xffffffffu, e, 1);
    float e_even = (lane & 1) ? s1 : e;
    float e_odd  = (lane & 1) ? e : s1;
    float s2e = __shfl_xor_sync(0xffffffffu, e_even, 2);
    float s2o = __shfl_xor_sync(0xffffffffu, e_odd, 2);
    float4 r;
    r.x = (lane & 2) ? s2e : e_even;
    r.z = (lane & 2) ? e_even : s2e;
    r.y = (lane & 2) ? s2o : e_odd;
    r.w = (lane & 2) ? e_odd : s2o;
    return r;
}

// ---------------- launch 2: k_edge — pairwise-interleaved score chains ----------------
__global__ __launch_bounds__(256, 3) void k_edge(const float* __restrict__ ke,
                                                 const float* __restrict__ ve,
                                                 const void* __restrict__ ei, int E) {
    __shared__ int s32s;
    if (threadIdx.x == 0) s32s = detect32(ei);
    __syncthreads();
    int is32 = s32s;
    int lane = threadIdx.x & 31;
    int hs = lane & 3;
    int gw = (blockIdx.x * blockDim.x + threadIdx.x) >> 5;
    int base = gw * 64;
    if (base >= E) return;
    int cnt = min(64, E - base);

    int pe_l[2], d_l[2];
    #pragma unroll
    for (int j = 0; j < 2; j++) {
        int idx = base + j * 32 + lane;
        if (idx < E) {
            pe_l[j] = g_perm[idx];
            d_l[j] = dst_at(ei, pe_l[j], is32);
        } else { pe_l[j] = 0; d_l[j] = -1; }
    }

    const float4* keL = (const float4*)ke + lane;
    const float4* veL = (const float4*)ve + lane;

    int i1 = (1 < cnt) ? 1 : 0;
    int pa = __shfl_sync(0xffffffffu, pe_l[0], 0);
    int pb = __shfl_sync(0xffffffffu, pe_l[i1 >> 5], i1 & 31);
    float4 k0 = __ldg(keL + (size_t)pa * 32), v0 = __ldg(veL + (size_t)pa * 32);
    float4 k1 = __ldg(keL + (size_t)pb * 32), v1 = __ldg(veL + (size_t)pb * 32);

    float4 wt0, wt1, wt2, wt3;
    wt0 = wt1 = wt2 = wt3 = make_float4(0.f, 0.f, 0.f, 0.f);
    float c_h = 0.f;
    float4 a0 = make_float4(0.f, 0.f, 0.f, 0.f), a1 = a0, a2 = a0, a3 = a0;
    float aden = 0.f;
    int prevd = -1;

    #define LOADWT(dd) do { \
        const float4* bw = (const float4*)(g_wt + (size_t)(dd) * 512) + lane; \
        wt0 = __ldg(bw); wt1 = __ldg(bw + 32); wt2 = __ldg(bw + 64); wt3 = __ldg(bw + 96); \
        c_h = __ldg(&g_c[(dd) * 4 + hs]); \
    } while (0)

    #define FLUSHSEG(dd) do { \
        float* S = g_S + (size_t)(dd) * 512 + lane * 4; \
        atomicAdd(S + 0,   a0.x); atomicAdd(S + 1,   a0.y); atomicAdd(S + 2,   a0.z); atomicAdd(S + 3,   a0.w); \
        atomicAdd(S + 128, a1.x); atomicAdd(S + 129, a1.y); atomicAdd(S + 130, a1.z); atomicAdd(S + 131, a1.w); \
        atomicAdd(S + 256, a2.x); atomicAdd(S + 257, a2.y); atomicAdd(S + 258, a2.z); atomicAdd(S + 259, a2.w); \
        atomicAdd(S + 384, a3.x); atomicAdd(S + 385, a3.y); atomicAdd(S + 386, a3.z); atomicAdd(S + 387, a3.w); \
        if (lane < 4) atomicAdd(&g_den[(dd) * 4 + lane], aden); \
        a0 = a1 = a2 = a3 = make_float4(0.f, 0.f, 0.f, 0.f); \
        aden = 0.f; \
    } while (0)

    #define DOTS(K, r0, r1, r2, r3) do { \
        r0 = K.x * wt0.x + K.y * wt0.y + K.z * wt0.z + K.w * wt0.w; \
        r1 = K.x * wt1.x + K.y * wt1.y + K.z * wt1.z + K.w * wt1.w; \
        r2 = K.x * wt2.x + K.y * wt2.y + K.z * wt2.z + K.w * wt2.w; \
        r3 = K.x * wt3.x + K.y * wt3.y + K.z * wt3.z + K.w * wt3.w; \
    } while (0)

    #define ACCUM(EV, V) do { \
        a0.x += EV.x * V.x; a0.y += EV.x * V.y; a0.z += EV.x * V.z; a0.w += EV.x * V.w; \
        a1.x += EV.y * V.x; a1.y += EV.y * V.y; a1.z += EV.y * V.z; a1.w += EV.y * V.w; \
        a2.x += EV.z * V.x; a2.y += EV.z * V.y; a2.z += EV.z * V.z; a2.w += EV.z * V.w; \
        a3.x += EV.w * V.x; a3.y += EV.w * V.y; a3.z += EV.w * V.z; a3.w += EV.w * V.w; \
        aden += (hs == 0) ? EV.x : (hs == 1) ? EV.y : (hs == 2) ? EV.z : EV.w; \
    } while (0)

    int i = 0;
    for (; i + 1 < cnt; i += 2) {
        int inx2 = (i + 2 < cnt) ? i + 2 : i;
        int inx3 = (i + 3 < cnt) ? i + 3 : inx2;
        int pn2 = __shfl_sync(0xffffffffu, pe_l[inx2 >> 5], inx2 & 31);
        int pn3 = __shfl_sync(0xffffffffu, pe_l[inx3 >> 5], inx3 & 31);
        float4 k2 = __ldg(keL + (size_t)pn2 * 32);
        float4 v2 = __ldg(veL + (size_t)pn2 * 32);
        float4 k3 = __ldg(keL + (size_t)pn3 * 32);
        float4 v3 = __ldg(veL + (size_t)pn3 * 32);

        int d0 = __shfl_sync(0xffffffffu, d_l[i >> 5], i & 31);
        int d1 = __shfl_sync(0xffffffffu, d_l[(i + 1) >> 5], (i + 1) & 31);

        if (d0 != prevd) {
            if (prevd >= 0) FLUSHSEG(prevd);
            LOADWT(d0);
            prevd = d0;
        }
        float q0, q1, q2, q3;
        DOTS(k0, q0, q1, q2, q3);
        if (d1 == d0) {
            float p0, p1, p2, p3;
            DOTS(k1, p0, p1, p2, p3);
            float4 eA = score4(q0, q1, q2, q3, lane, c_h);
            float4 eB = score4(p0, p1, p2, p3, lane, c_h);
            ACCUM(eA, v0);
            ACCUM(eB, v1);
        } else {
            float4 eA = score4(q0, q1, q2, q3, lane, c_h);
            ACCUM(eA, v0);
            FLUSHSEG(prevd);
            LOADWT(d1);
            prevd = d1;
            float p0, p1, p2, p3;
            DOTS(k1, p0, p1, p2, p3);
            float4 eB = score4(p0, p1, p2, p3, lane, c_h);
            ACCUM(eB, v1);
        }
        k0 = k2; v0 = v2; k1 = k3; v1 = v3;
    }
    if (i < cnt) {
        int d0 = __shfl_sync(0xffffffffu, d_l[i >> 5], i & 31);
        if (d0 != prevd) {
            if (prevd >= 0) FLUSHSEG(prevd);
            LOADWT(d0);
            prevd = d0;
        }
        float q0, q1, q2, q3;
        DOTS(k0, q0, q1, q2, q3);
        float4 eA = score4(q0, q1, q2, q3, lane, c_h);
        ACCUM(eA, v0);
    }
    FLUSHSEG(prevd);
    #undef LOADWT
    #undef FLUSHSEG
    #undef DOTS
    #undef ACCUM
}

// ---------------- launch 3 (PROFILED): k_post — 16-node tiles ----------------
__global__ __launch_bounds__(256) void k_post(const float* __restrict__ Wv,
                                              const float* __restrict__ bv,
                                              const float* __restrict__ Wo,
                                              const float* __restrict__ bo,
                                              float* __restrict__ Y, int n) {
    extern __shared__ float sq[];
    float* Ss = sq;               // [16][4][136]
    float* As = sq + 16 * 544;    // [16][132]
    int tid = threadIdx.x;
    int row0 = blockIdx.x * 16;

    for (int i = tid; i < 16 * 512; i += 256) {
        int nl = i >> 9, rest = i & 511;
        int h = rest >> 7, d = rest & 127;
        int gr = row0 + nl;
        float v = 0.f;
        if (gr < n) {
            size_t idx = (size_t)gr * 512 + rest;
            v = g_S[idx];
            g_S[idx] = 0.f;
        }
        Ss[nl * 544 + h * 136 + d] = v;
    }
    __syncthreads();

    int cg = (tid & 31) * 4, rg = (tid >> 5) * 2;
    int h = cg >> 5;
    {
        float acc[2][4] = {};
        #pragma unroll 8
        for (int d = 0; d < DIM; d++) {
            float4 wv = __ldg((const float4*)&Wv[d * DIM + cg]);
            float a0 = Ss[(rg + 0) * 544 + h * 136 + d];
            float a1 = Ss[(rg + 1) * 544 + h * 136 + d];
            acc[0][0] += a0 * wv.x; acc[0][1] += a0 * wv.y; acc[0][2] += a0 * wv.z; acc[0][3] += a0 * wv.w;
            acc[1][0] += a1 * wv.x; acc[1][1] += a1 * wv.y; acc[1][2] += a1 * wv.z; acc[1][3] += a1 * wv.w;
        }
        float4 bb = __ldg((const float4*)&bv[cg]);
        #pragma unroll
        for (int rr = 0; rr < 2; rr++) {
            int gr = row0 + rg + rr;
            float4 o = make_float4(0.f, 0.f, 0.f, 0.f);
            if (gr < n) {
                float den = g_den[gr * HEADS + h];
                if (den > 0.f) {
                    float inv = 1.f / den;
                    o = make_float4(acc[rr][0] * inv + bb.x, acc[rr][1] * inv + bb.y,
                                    acc[rr][2] * inv + bb.z, acc[rr][3] * inv + bb.w);
                }
            }
            As[(rg + rr) * 132 + cg + 0] = o.x;
            As[(rg + rr) * 132 + cg + 1] = o.y;
            As[(rg + rr) * 132 + cg + 2] = o.z;
            As[(rg + rr) * 132 + cg + 3] = o.w;
        }
    }
    __syncthreads();

    if (tid < 64) {
        int gr = row0 + (tid >> 2);
        if (gr < n) g_den[gr * HEADS + (tid & 3)] = 0.f;
    }

    {
        float acc[2][4] = {};
        #pragma unroll 8
        for (int d = 0; d < DIM; d++) {
            float4 w = __ldg((const float4*)&Wo[d * DIM + cg]);
            float a0 = As[(rg + 0) * 132 + d];
            float a1 = As[(rg + 1) * 132 + d];
            acc[0][0] += a0 * w.x; acc[0][1] += a0 * w.y; acc[0][2] += a0 * w.z; acc[0][3] += a0 * w.w;
            acc[1][0] += a1 * w.x; acc[1][1] += a1 * w.y; acc[1][2] += a1 * w.z; acc[1][3] += a1 * w.w;
        }
        float4 bb = __ldg((const float4*)&bo[cg]);
        #pragma unroll
        for (int rr = 0; rr < 2; rr++) {
            int gr = row0 + rg + rr;
            if (gr < n) {
                float4 o = make_float4(acc[rr][0] + bb.x, acc[rr][1] + bb.y,
                                       acc[rr][2] + bb.z, acc[rr][3] + bb.w);
                *(float4*)&Y[gr * DIM + cg] = o;
            }
        }
    }
}

extern "C" void kernel_launch(void* const* d_in, const int* in_sizes, int n_in,
                              void* d_out, int out_size) {
    const float* q_nodes = (const float*)d_in[0];
    const float* k_edges = (const float*)d_in[1];
    const float* v_edges = (const float*)d_in[2];
    const float* Wq = (const float*)d_in[3];
    const float* bq = (const float*)d_in[4];
    const float* Wk = (const float*)d_in[5];
    const float* bk = (const float*)d_in[6];
    const float* Wv = (const float*)d_in[7];
    const float* bv = (const float*)d_in[8];
    const float* Wo = (const float*)d_in[9];
    const float* bo = (const float*)d_in[10];
    const void*  ei = (const void*)d_in[11];

    int N = in_sizes[0] / DIM;
    int E = in_sizes[1] / DIM;

    int dev = 0, sms = 148;
    cudaGetDevice(&dev);
    cudaDeviceGetAttribute(&sms, cudaDevAttrMultiProcessorCount, dev);
    int nb = sms * 2;   // all-resident by __launch_bounds__(256,2)

    const int smem_node = 32 * 132 * (int)sizeof(float);              // 16896
    const int smem_post = (16 * 544 + 16 * 132) * (int)sizeof(float); // 43264
    cudaFuncSetAttribute(k_node, cudaFuncAttributeMaxDynamicSharedMemorySize, smem_node);
    cudaFuncSetAttribute(k_post, cudaFuncAttributeMaxDynamicSharedMemorySize, smem_post);

    int histBlocks = (E + 255) / 256;
    int postBlocks = (N + 15) / 16;
    int ewarps = (E + 63) / 64;
    int eblocks = (ewarps + 7) / 8;

    k_hist<<<histBlocks, 256>>>(ei, E);                                          // 0
    k_node<<<nb, 256, smem_node>>>(q_nodes, Wq, bq, Wk, bk, ei, N, E, nb);       // 1
    k_edge<<<eblocks, 256>>>(k_edges, v_edges, ei, E);                           // 2
    k_post<<<postBlocks, 256, smem_post>>>(Wv, bv, Wo, bo, (float*)d_out, N);    // 3 (profiled)
}